// round 7
// baseline (speedup 1.0000x reference)
#include <cuda_runtime.h>
#include <cuda_bf16.h>
#include <math.h>
#include <stdint.h>

// Problem shapes (fixed by reference)
#define T_STEPS 512
#define BATCH   256
#define NIN     1024
#define NH      1024
#define M_TOTAL (T_STEPS * BATCH)   // 131072

// ============================================================================
// Device scratch (static — no allocation allowed)
// ============================================================================
__device__ __nv_bfloat16 g_Ahi[(size_t)M_TOTAL * NIN];   // inputs hi, [M][K]
__device__ __nv_bfloat16 g_Alo[(size_t)M_TOTAL * NIN];   // inputs lo
__device__ __nv_bfloat16 g_Wxh_hi[(size_t)NH * NIN];     // W_xh^T hi, [N][K]
__device__ __nv_bfloat16 g_Wxh_lo[(size_t)NH * NIN];
__device__ __nv_bfloat16 g_Whh_hi[(size_t)NH * NH];      // W_hh^T hi, [N][K]
__device__ __nv_bfloat16 g_Whh_lo[(size_t)NH * NH];
__device__ __nv_bfloat16 g_Hhi[2][(size_t)BATCH * NH];   // state hi, double buffered
__device__ __nv_bfloat16 g_Hlo[2][(size_t)BATCH * NH];

// End-of-kernel group barrier (4 groups); zero-init, phase monotonic
__device__ unsigned g_bar_count[4];
__device__ unsigned g_bar_phase[4];
// Per-CTA progress flags: flag[mb][nb][0] = latest step whose H is published.
// Padded to 128 B per flag to avoid line sharing. Reset to 0 at kernel end.
__device__ unsigned g_flag[4][32][32];

// ============================================================================
// PTX helpers (all sm_80-era: compile for plain compute_103)
// ============================================================================
__device__ __forceinline__ uint32_t smem_u32(const void* p) {
    uint32_t a;
    asm("{ .reg .u64 t; cvta.to.shared.u64 t, %1; cvt.u32.u64 %0, t; }"
        : "=r"(a) : "l"(p));
    return a;
}

#define CP16(dst, src) \
    asm volatile("cp.async.cg.shared.global [%0], [%1], 16;" :: "r"(dst), "l"(src))
#define CP_COMMIT() asm volatile("cp.async.commit_group;" ::: "memory")
#define CP_WAIT(n)  asm volatile("cp.async.wait_group %0;" :: "n"(n) : "memory")

__device__ __forceinline__ void ldsm4(uint32_t r[4], uint32_t addr) {
    asm volatile("ldmatrix.sync.aligned.m8n8.x4.shared.b16 {%0,%1,%2,%3}, [%4];"
                 : "=r"(r[0]), "=r"(r[1]), "=r"(r[2]), "=r"(r[3]) : "r"(addr));
}

__device__ __forceinline__ void mma_bf16(float c[4], const uint32_t a[4],
                                         const uint32_t b[2]) {
    asm volatile(
        "mma.sync.aligned.m16n8k16.row.col.f32.bf16.bf16.f32 "
        "{%0,%1,%2,%3}, {%4,%5,%6,%7}, {%8,%9}, {%0,%1,%2,%3};"
        : "+f"(c[0]), "+f"(c[1]), "+f"(c[2]), "+f"(c[3])
        : "r"(a[0]), "r"(a[1]), "r"(a[2]), "r"(a[3]), "r"(b[0]), "r"(b[1]));
}

__device__ __forceinline__ unsigned ld_acq(const unsigned* p) {
    unsigned v;
    asm volatile("ld.acquire.gpu.global.u32 %0, [%1];" : "=r"(v) : "l"(p) : "memory");
    return v;
}
__device__ __forceinline__ void st_rel(unsigned* p, unsigned v) {
    asm volatile("st.release.gpu.global.u32 [%0], %1;" :: "l"(p), "r"(v) : "memory");
}

// Spin until *p >= tgt (acquire on success).
__device__ __forceinline__ void wait_flag(const unsigned* p, unsigned tgt) {
    while (ld_acq(p) < tgt) { }
}

#define PK_CTAS  128
#define PK_GROUP 32   // CTAs per m-group barrier

__device__ __forceinline__ void grid_bar(int g) {
    unsigned ph = ld_acq(&g_bar_phase[g]);
    __threadfence();
    unsigned old = atomicAdd(&g_bar_count[g], 1);
    if (old == PK_GROUP - 1) {
        g_bar_count[g] = 0;
        st_rel(&g_bar_phase[g], ph + 1);
    } else {
        while (ld_acq(&g_bar_phase[g]) == ph) { }
    }
}

// ============================================================================
// Prep: split + transpose a weight [K][N] fp32 -> [N][K] bf16 hi/lo
// ============================================================================
__global__ __launch_bounds__(256) void split_w_kernel(const float* __restrict__ W,
                                                      int which)
{
    __shared__ float tile[32][33];
    __nv_bfloat16* hiOut = which ? g_Whh_hi : g_Wxh_hi;
    __nv_bfloat16* loOut = which ? g_Whh_lo : g_Wxh_lo;
    const int bx = blockIdx.x * 32;   // n block
    const int by = blockIdx.y * 32;   // k block
    const int tx = threadIdx.x & 31;
    const int ty = threadIdx.x >> 5;
    for (int i = ty; i < 32; i += 8)
        tile[i][tx] = W[(size_t)(by + i) * NH + bx + tx];
    __syncthreads();
    for (int i = ty; i < 32; i += 8) {
        float x = tile[tx][i];                 // W[by+tx][bx+i]
        __nv_bfloat16 h = __float2bfloat16(x);
        __nv_bfloat16 l = __float2bfloat16(x - __bfloat162float(h));
        size_t o = (size_t)(bx + i) * NIN + by + tx;
        hiOut[o] = h;
        loOut[o] = l;
    }
}

// ============================================================================
// Prep: split inputs fp32 [M][K] -> g_Ahi/g_Alo bf16 (same layout)
// ============================================================================
__global__ __launch_bounds__(256) void split_a_kernel(const float* __restrict__ A)
{
    const size_t n4 = (size_t)M_TOTAL * NIN / 4;
    size_t i = (size_t)blockIdx.x * blockDim.x + threadIdx.x;
    const size_t stride = (size_t)gridDim.x * blockDim.x;
    for (; i < n4; i += stride) {
        float4 v = ((const float4*)A)[i];
        __nv_bfloat16 h0 = __float2bfloat16(v.x);
        __nv_bfloat16 h1 = __float2bfloat16(v.y);
        __nv_bfloat16 h2 = __float2bfloat16(v.z);
        __nv_bfloat16 h3 = __float2bfloat16(v.w);
        __nv_bfloat162 hp0(h0, h1), hp1(h2, h3);
        __nv_bfloat162 lp0(__float2bfloat16(v.x - __bfloat162float(h0)),
                           __float2bfloat16(v.y - __bfloat162float(h1)));
        __nv_bfloat162 lp1(__float2bfloat16(v.z - __bfloat162float(h2)),
                           __float2bfloat16(v.w - __bfloat162float(h3)));
        ((__nv_bfloat162*)g_Ahi)[i * 2 + 0] = hp0;
        ((__nv_bfloat162*)g_Ahi)[i * 2 + 1] = hp1;
        ((__nv_bfloat162*)g_Alo)[i * 2 + 0] = lp0;
        ((__nv_bfloat162*)g_Alo)[i * 2 + 1] = lp1;
    }
}

// ============================================================================
// Phase 1 GEMM: C[M,N] = Ahi/lo @ Whi/lo^T + bias  (split bf16, HMMA)
// CTA 128x128, 256 thr (8 warps 2x4, warp tile 64x32), K-chunk 32, 3 stages.
// (R5 configuration — best measured.)
// ============================================================================
#define G1_PITCH   40
#define G1_ARR_B   (128 * G1_PITCH * 2)      // 10240 B per array
#define G1_STAGE_B (4 * G1_ARR_B)            // 40960 B per stage
#define G1_SMEM    (3 * G1_STAGE_B)          // 122880 B

__global__ __launch_bounds__(256, 1) void gemm1_kernel(
    const float* __restrict__ bias, float* __restrict__ C)
{
    extern __shared__ char smem[];
    const uint32_t sb0 = smem_u32(smem);
    const int tid  = threadIdx.x;
    const int wid  = tid >> 5;
    const int lane = tid & 31;
    const int m0 = blockIdx.y * 128;
    const int n0 = blockIdx.x * 128;
    const int warp_m = (wid >> 2) * 64;
    const int warp_n = (wid & 3) * 32;

    float acc[4][4][4];
#pragma unroll
    for (int i = 0; i < 4; i++)
#pragma unroll
        for (int j = 0; j < 4; j++)
#pragma unroll
            for (int k = 0; k < 4; k++) acc[i][j][k] = 0.f;

    const int crow = tid >> 2;       // 0..63
    const int cseg = tid & 3;        // 0..3 (16B units)

    auto issue = [&](int c, int s) {
        const uint32_t st = sb0 + s * G1_STAGE_B;
        const int kb = c * 32 + cseg * 8;
#pragma unroll
        for (int h = 0; h < 2; h++) {
            const int r = crow + h * 64;
            const size_t ga = (size_t)(m0 + r) * NIN + kb;
            const size_t gb = (size_t)(n0 + r) * NIN + kb;
            const uint32_t so = r * 80 + cseg * 16;
            CP16(st + so,                  g_Ahi + ga);
            CP16(st + G1_ARR_B + so,       g_Alo + ga);
            CP16(st + 2 * G1_ARR_B + so,   g_Wxh_hi + gb);
            CP16(st + 3 * G1_ARR_B + so,   g_Wxh_lo + gb);
        }
    };

    issue(0, 0); CP_COMMIT();
    issue(1, 1); CP_COMMIT();

    for (int it = 0; it < 32; it++) {
        CP_WAIT(1);
        __syncthreads();
        if (it + 2 < 32) issue(it + 2, (it + 2) % 3);
        CP_COMMIT();

        const uint32_t st = sb0 + (it % 3) * G1_STAGE_B;
#pragma unroll
        for (int ks = 0; ks < 2; ks++) {
            const uint32_t kb = ks * 32;
            uint32_t ah[4][4], al[4][4];
#pragma unroll
            for (int mt = 0; mt < 4; mt++) {
                const int mr = warp_m + mt * 16 + (lane & 15);
                const uint32_t ad = st + mr * 80 + ((lane >> 4) * 16) + kb;
                ldsm4(ah[mt], ad);
                ldsm4(al[mt], ad + G1_ARR_B);
            }
            uint32_t bh[4][2], bl[4][2];
#pragma unroll
            for (int g = 0; g < 2; g++) {
                const int nr = warp_n + g * 16 + (lane & 7) + ((lane >> 4) << 3);
                const uint32_t bd = st + 2 * G1_ARR_B + nr * 80 +
                                    (((lane >> 3) & 1) * 16) + kb;
                uint32_t t[4];
                ldsm4(t, bd);
                bh[g * 2][0] = t[0]; bh[g * 2][1] = t[1];
                bh[g * 2 + 1][0] = t[2]; bh[g * 2 + 1][1] = t[3];
                ldsm4(t, bd + G1_ARR_B);
                bl[g * 2][0] = t[0]; bl[g * 2][1] = t[1];
                bl[g * 2 + 1][0] = t[2]; bl[g * 2 + 1][1] = t[3];
            }
#pragma unroll
            for (int mt = 0; mt < 4; mt++)
#pragma unroll
                for (int nt = 0; nt < 4; nt++) {
                    mma_bf16(acc[mt][nt], ah[mt], bh[nt]);
                    mma_bf16(acc[mt][nt], ah[mt], bl[nt]);
                    mma_bf16(acc[mt][nt], al[mt], bh[nt]);
                }
        }
    }

#pragma unroll
    for (int mt = 0; mt < 4; mt++) {
        const int m = m0 + warp_m + mt * 16 + (lane >> 2);
#pragma unroll
        for (int nt = 0; nt < 4; nt++) {
            const int n = n0 + warp_n + nt * 8 + (lane & 3) * 2;
            const float b0 = bias[n], b1 = bias[n + 1];
            float2 v0 = make_float2(acc[mt][nt][0] + b0, acc[mt][nt][1] + b1);
            float2 v1 = make_float2(acc[mt][nt][2] + b0, acc[mt][nt][3] + b1);
            *(float2*)(C + (size_t)m * NH + n)       = v0;
            *(float2*)(C + (size_t)(m + 8) * NH + n) = v1;
        }
    }
}

// ============================================================================
// t = 0: h0 = tanh(xw[0]); write fp32 out[0] and bf16 hi/lo state buf 0
// ============================================================================
__global__ __launch_bounds__(256) void tanh0_kernel(float* __restrict__ x)
{
    const size_t i = (size_t)blockIdx.x * blockDim.x + threadIdx.x;  // float4 idx
    float4 v = ((const float4*)x)[i];
    v.x = tanhf(v.x); v.y = tanhf(v.y); v.z = tanhf(v.z); v.w = tanhf(v.w);
    ((float4*)x)[i] = v;
    __nv_bfloat16 h0 = __float2bfloat16(v.x);
    __nv_bfloat16 h1 = __float2bfloat16(v.y);
    __nv_bfloat16 h2 = __float2bfloat16(v.z);
    __nv_bfloat16 h3 = __float2bfloat16(v.w);
    ((__nv_bfloat162*)g_Hhi[0])[i * 2 + 0] = __nv_bfloat162(h0, h1);
    ((__nv_bfloat162*)g_Hhi[0])[i * 2 + 1] = __nv_bfloat162(h2, h3);
    ((__nv_bfloat162*)g_Hlo[0])[i * 2 + 0] =
        __nv_bfloat162(__float2bfloat16(v.x - __bfloat162float(h0)),
                       __float2bfloat16(v.y - __bfloat162float(h1)));
    ((__nv_bfloat162*)g_Hlo[0])[i * 2 + 1] =
        __nv_bfloat162(__float2bfloat16(v.z - __bfloat162float(h2)),
                       __float2bfloat16(v.w - __bfloat162float(h3)));
}

// ============================================================================
// Persistent RNN recurrence: t = 1..511, FINE-GRAINED producer/consumer flags.
// 128 CTAs = 4 m-groups (64 rows) x 32 n-blocks (32 cols), 256 threads.
// W_hh hi+lo slice (32 n-rows x 1024 K) RESIDENT in smem (160 KB).
// H streamed per step: K-chunk 64, 3 stages x 20 KB, 16 iters/step.
// Chunk c (K-cols 64c..64c+64) of H[t-1] is produced by CTAs (mb,2c),(mb,2c+1);
// each consumer starts at its own chunk c0 = nb/2 and rotates, so the pipeline
// begins right after its own epilogue and CTAs stagger through K (de-bursting
// L2). Flags: flag[mb][nb] = t published with release after H[t] writes.
// ============================================================================
#define PW_HI    0
#define PW_LO    81920
#define PH_BASE  163840
#define PH_STAGE 20480
#define PH_SUB   5120
#define PH_LO    10240
#define PK_SMEM  225280

__global__ __launch_bounds__(256, 1) void rnn_persist_kernel(float* __restrict__ out)
{
    extern __shared__ char smem[];
    const uint32_t sb = smem_u32(smem);
    const int tid  = threadIdx.x;
    const int wid  = tid >> 5;
    const int lane = tid & 31;
    const int mb = blockIdx.x >> 5;    // 0..3  (m-group)
    const int nb = blockIdx.x & 31;    // 0..31
    const int m0 = mb * 64;
    const int n0 = nb * 32;
    const int warp_m = (wid >> 1) * 16;   // 0..48
    const int warp_n = (wid & 1) * 16;    // 0 or 16
    const int c0 = nb >> 1;               // rotation start chunk

    // ---- Load resident W_hh slice (hi+lo), chunked K-major, pitch 80B ----
    for (int idx = tid; idx < 4096; idx += 256) {
        const int ch  = idx >> 7;          // 0..31  k32-chunk
        const int r   = (idx >> 2) & 31;   // 0..31  n-row
        const int seg = idx & 3;           // 0..3   16B seg
        const size_t g = (size_t)(n0 + r) * NH + ch * 32 + seg * 8;
        const uint32_t so = sb + ch * 2560 + r * 80 + seg * 16;
        CP16(so + PW_HI, g_Whh_hi + g);
        CP16(so + PW_LO, g_Whh_lo + g);
    }
    CP_COMMIT(); CP_WAIT(0); __syncthreads();

    const int hrow = tid >> 2;   // 0..63
    const int hseg = tid & 3;

    for (int t = 1; t < T_STEPS; t++) {
        const __nv_bfloat16* Hh = g_Hhi[(t - 1) & 1];
        const __nv_bfloat16* Hl = g_Hlo[(t - 1) & 1];
        __nv_bfloat16* HhO = g_Hhi[t & 1];
        __nv_bfloat16* HlO = g_Hlo[t & 1];
        float* X = out + (size_t)t * BATCH * NH;
        const unsigned tgt = (unsigned)(t - 1);

        // wait for producers of chunk-seq i, then issue its H loads (stage i%3)
        auto waitIssue = [&](int i) {
            const int c = (c0 + i) & 15;   // absolute K64 chunk
            wait_flag(&g_flag[mb][2 * c][0],     tgt);
            wait_flag(&g_flag[mb][2 * c + 1][0], tgt);
            const uint32_t st = sb + PH_BASE + (i % 3) * PH_STAGE +
                                hrow * 80 + hseg * 16;
#pragma unroll
            for (int j = 0; j < 2; j++) {
                const size_t ga = (size_t)(m0 + hrow) * NH + c * 64 + j * 32 + hseg * 8;
                CP16(st + j * PH_SUB,         Hh + ga);
                CP16(st + j * PH_SUB + PH_LO, Hl + ga);
            }
        };
        waitIssue(0); CP_COMMIT();
        waitIssue(1); CP_COMMIT();

        // Prefetch this CTA's xw tile into registers
        float2 xwr[2][2];
        {
            const int mrow = m0 + warp_m + (lane >> 2);
#pragma unroll
            for (int half = 0; half < 2; half++)
#pragma unroll
                for (int nt = 0; nt < 2; nt++) {
                    const int m = mrow + half * 8;
                    const int n = n0 + warp_n + nt * 8 + (lane & 3) * 2;
                    xwr[half][nt] = *(const float2*)(X + (size_t)m * NH + n);
                }
        }

        // Split-K accumulators: [kpar][nt][4]
        float acc[2][2][4];
#pragma unroll
        for (int p = 0; p < 2; p++)
#pragma unroll
            for (int i = 0; i < 2; i++)
#pragma unroll
                for (int j = 0; j < 4; j++) acc[p][i][j] = 0.f;

        for (int it = 0; it < 16; it++) {
            CP_WAIT(1);
            __syncthreads();
            if (it + 2 < 16) waitIssue(it + 2);
            CP_COMMIT();

            const int c = (c0 + it) & 15;   // absolute chunk being computed
            const uint32_t hst = sb + PH_BASE + (it % 3) * PH_STAGE;
#pragma unroll
            for (int ks = 0; ks < 4; ks++) {
                const int sub = ks >> 1;
                const int kp  = ks & 1;
                const uint32_t kb = (ks & 1) * 32;
                uint32_t ah[4], al[4];
                {
                    const uint32_t ad = hst + sub * PH_SUB +
                                        (warp_m + (lane & 15)) * 80 +
                                        ((lane >> 4) * 16) + kb;
                    ldsm4(ah, ad);
                    ldsm4(al, ad + PH_LO);
                }
                uint32_t bh[2][2], bl[2][2];
                {
                    const int nr = warp_n + (lane & 7) + ((lane >> 4) << 3);
                    const uint32_t bd = sb + (c * 2 + sub) * 2560 + nr * 80 +
                                        (((lane >> 3) & 1) * 16) + kb;
                    uint32_t tmp[4];
                    ldsm4(tmp, bd + PW_HI);
                    bh[0][0] = tmp[0]; bh[0][1] = tmp[1];
                    bh[1][0] = tmp[2]; bh[1][1] = tmp[3];
                    ldsm4(tmp, bd + PW_LO);
                    bl[0][0] = tmp[0]; bl[0][1] = tmp[1];
                    bl[1][0] = tmp[2]; bl[1][1] = tmp[3];
                }
#pragma unroll
                for (int nt = 0; nt < 2; nt++) mma_bf16(acc[kp][nt], ah, bh[nt]);
#pragma unroll
                for (int nt = 0; nt < 2; nt++) mma_bf16(acc[kp][nt], ah, bl[nt]);
#pragma unroll
                for (int nt = 0; nt < 2; nt++) mma_bf16(acc[kp][nt], al, bh[nt]);
            }
        }

        // ---- Epilogue: h = tanh(xw + acc0 + acc1); write out + bf16 state ----
        {
            const int mrow = m0 + warp_m + (lane >> 2);
#pragma unroll
            for (int half = 0; half < 2; half++) {
                const int m = mrow + half * 8;
#pragma unroll
                for (int nt = 0; nt < 2; nt++) {
                    const int n = n0 + warp_n + nt * 8 + (lane & 3) * 2;
                    const size_t off = (size_t)m * NH + n;
                    const float s0 = acc[0][nt][half * 2 + 0] + acc[1][nt][half * 2 + 0];
                    const float s1 = acc[0][nt][half * 2 + 1] + acc[1][nt][half * 2 + 1];
                    const float v0 = tanhf(xwr[half][nt].x + s0);
                    const float v1 = tanhf(xwr[half][nt].y + s1);
                    *(float2*)(X + off) = make_float2(v0, v1);
                    const __nv_bfloat16 h0 = __float2bfloat16(v0);
                    const __nv_bfloat16 h1 = __float2bfloat16(v1);
                    *(__nv_bfloat162*)(HhO + off) = __nv_bfloat162(h0, h1);
                    *(__nv_bfloat162*)(HlO + off) = __nv_bfloat162(
                        __float2bfloat16(v0 - __bfloat162float(h0)),
                        __float2bfloat16(v1 - __bfloat162float(h1)));
                    if (t == T_STEPS - 1)
                        *(float2*)(out + (size_t)T_STEPS * BATCH * NH + off) =
                            make_float2(v0, v1);
                }
            }
        }

        // ---- Publish: all writers fence, then one release store of flag=t ----
        __threadfence();
        __syncthreads();
        if (tid == 0) st_rel(&g_flag[mb][nb][0], (unsigned)t);
    }

    // ---- End of launch: group barrier, then reset flags for next replay ----
    __syncthreads();
    if (tid == 0) {
        grid_bar(mb);
        g_flag[mb][nb][0] = 0;   // visible at kernel completion boundary
    }
}

// ============================================================================
// Launch
// ============================================================================
extern "C" void kernel_launch(void* const* d_in, const int* in_sizes, int n_in,
                              void* d_out, int out_size)
{
    const float* inputs = (const float*)d_in[0];   // [T, B, NIN]
    const float* W_xh   = (const float*)d_in[1];   // [NIN, NH]
    const float* W_hh   = (const float*)d_in[2];   // [NH, NH]
    const float* b_h    = (const float*)d_in[3];   // [NH]
    float* out = (float*)d_out;                    // [T, B, NH] + [B, NH]

    const size_t step_elems = (size_t)BATCH * NH;  // 262144

    static bool attr_set = false;
    if (!attr_set) {
        cudaFuncSetAttribute(gemm1_kernel,
                             cudaFuncAttributeMaxDynamicSharedMemorySize, G1_SMEM);
        cudaFuncSetAttribute(rnn_persist_kernel,
                             cudaFuncAttributeMaxDynamicSharedMemorySize, PK_SMEM);
        attr_set = true;
    }

    // Prep: split weights (transposed) and inputs into bf16 hi/lo
    {
        dim3 grid(NH / 32, NIN / 32);
        split_w_kernel<<<grid, 256>>>(W_xh, 0);
        split_w_kernel<<<grid, 256>>>(W_hh, 1);
        split_a_kernel<<<8192, 256>>>(inputs);
    }

    // Phase 1: xw = inputs @ W_xh + b_h  -> out[0..T)
    {
        dim3 grid(NH / 128, M_TOTAL / 128);   // (8, 1024)
        gemm1_kernel<<<grid, 256, G1_SMEM>>>(b_h, out);
    }

    // t = 0
    tanh0_kernel<<<(int)(step_elems / 4 / 256), 256>>>(out);

    // t = 1..T-1 in ONE persistent kernel (also writes final_state tail)
    rnn_persist_kernel<<<PK_CTAS, 256, PK_SMEM>>>(out);
}

// round 8
// speedup vs baseline: 1.7562x; 1.7562x over previous
#include <cuda_runtime.h>
#include <cuda_bf16.h>
#include <math.h>
#include <stdint.h>

// Problem shapes (fixed by reference)
#define T_STEPS 512
#define BATCH   256
#define NIN     1024
#define NH      1024
#define M_TOTAL (T_STEPS * BATCH)   // 131072

// ============================================================================
// Device scratch (static — no allocation allowed)
// ============================================================================
__device__ __nv_bfloat16 g_Ahi[(size_t)M_TOTAL * NIN];   // inputs hi, [M][K]
__device__ __nv_bfloat16 g_Alo[(size_t)M_TOTAL * NIN];   // inputs lo
__device__ __nv_bfloat16 g_Wxh_hi[(size_t)NH * NIN];     // W_xh^T hi, [N][K]
__device__ __nv_bfloat16 g_Wxh_lo[(size_t)NH * NIN];
__device__ __nv_bfloat16 g_Whh_hi[(size_t)NH * NH];      // W_hh^T hi, [N][K]
__device__ __nv_bfloat16 g_Whh_lo[(size_t)NH * NH];
__device__ __nv_bfloat16 g_Hhi[2][(size_t)BATCH * NH];   // state hi, double buffered
__device__ __nv_bfloat16 g_Hlo[2][(size_t)BATCH * NH];

// Per-m-group barrier state (4 groups of 32 CTAs); zero-init, phase monotonic
__device__ unsigned g_bar_count[4];
__device__ unsigned g_bar_phase[4];

// ============================================================================
// PTX helpers (all sm_80-era: compile for plain compute_103)
// ============================================================================
__device__ __forceinline__ uint32_t smem_u32(const void* p) {
    uint32_t a;
    asm("{ .reg .u64 t; cvta.to.shared.u64 t, %1; cvt.u32.u64 %0, t; }"
        : "=r"(a) : "l"(p));
    return a;
}

#define CP16(dst, src) \
    asm volatile("cp.async.cg.shared.global [%0], [%1], 16;" :: "r"(dst), "l"(src))
#define CP_COMMIT() asm volatile("cp.async.commit_group;" ::: "memory")
#define CP_WAIT(n)  asm volatile("cp.async.wait_group %0;" :: "n"(n) : "memory")

__device__ __forceinline__ void ldsm4(uint32_t r[4], uint32_t addr) {
    asm volatile("ldmatrix.sync.aligned.m8n8.x4.shared.b16 {%0,%1,%2,%3}, [%4];"
                 : "=r"(r[0]), "=r"(r[1]), "=r"(r[2]), "=r"(r[3]) : "r"(addr));
}

__device__ __forceinline__ void mma_bf16(float c[4], const uint32_t a[4],
                                         const uint32_t b[2]) {
    asm volatile(
        "mma.sync.aligned.m16n8k16.row.col.f32.bf16.bf16.f32 "
        "{%0,%1,%2,%3}, {%4,%5,%6,%7}, {%8,%9}, {%0,%1,%2,%3};"
        : "+f"(c[0]), "+f"(c[1]), "+f"(c[2]), "+f"(c[3])
        : "r"(a[0]), "r"(a[1]), "r"(a[2]), "r"(a[3]), "r"(b[0]), "r"(b[1]));
}

__device__ __forceinline__ unsigned ld_acq(const unsigned* p) {
    unsigned v;
    asm volatile("ld.acquire.gpu.global.u32 %0, [%1];" : "=r"(v) : "l"(p) : "memory");
    return v;
}
__device__ __forceinline__ void st_rel(unsigned* p, unsigned v) {
    asm volatile("st.release.gpu.global.u32 [%0], %1;" :: "l"(p), "r"(v) : "memory");
}

#define PK_CTAS  128
#define PK_GROUP 32   // CTAs per m-group barrier

__device__ __forceinline__ void grid_bar(int g) {
    unsigned ph = ld_acq(&g_bar_phase[g]);
    __threadfence();
    unsigned old = atomicAdd(&g_bar_count[g], 1);
    if (old == PK_GROUP - 1) {
        g_bar_count[g] = 0;
        st_rel(&g_bar_phase[g], ph + 1);
    } else {
        while (ld_acq(&g_bar_phase[g]) == ph) { }
    }
}

// ============================================================================
// Prep: split + transpose a weight [K][N] fp32 -> [N][K] bf16 hi/lo
// ============================================================================
__global__ __launch_bounds__(256) void split_w_kernel(const float* __restrict__ W,
                                                      int which)
{
    __shared__ float tile[32][33];
    __nv_bfloat16* hiOut = which ? g_Whh_hi : g_Wxh_hi;
    __nv_bfloat16* loOut = which ? g_Whh_lo : g_Wxh_lo;
    const int bx = blockIdx.x * 32;   // n block
    const int by = blockIdx.y * 32;   // k block
    const int tx = threadIdx.x & 31;
    const int ty = threadIdx.x >> 5;
    for (int i = ty; i < 32; i += 8)
        tile[i][tx] = W[(size_t)(by + i) * NH + bx + tx];
    __syncthreads();
    for (int i = ty; i < 32; i += 8) {
        float x = tile[tx][i];                 // W[by+tx][bx+i]
        __nv_bfloat16 h = __float2bfloat16(x);
        __nv_bfloat16 l = __float2bfloat16(x - __bfloat162float(h));
        size_t o = (size_t)(bx + i) * NIN + by + tx;
        hiOut[o] = h;
        loOut[o] = l;
    }
}

// ============================================================================
// Prep: split inputs fp32 [M][K] -> g_Ahi/g_Alo bf16 (same layout)
// ============================================================================
__global__ __launch_bounds__(256) void split_a_kernel(const float* __restrict__ A)
{
    const size_t n4 = (size_t)M_TOTAL * NIN / 4;
    size_t i = (size_t)blockIdx.x * blockDim.x + threadIdx.x;
    const size_t stride = (size_t)gridDim.x * blockDim.x;
    for (; i < n4; i += stride) {
        float4 v = ((const float4*)A)[i];
        __nv_bfloat16 h0 = __float2bfloat16(v.x);
        __nv_bfloat16 h1 = __float2bfloat16(v.y);
        __nv_bfloat16 h2 = __float2bfloat16(v.z);
        __nv_bfloat16 h3 = __float2bfloat16(v.w);
        __nv_bfloat162 hp0(h0, h1), hp1(h2, h3);
        __nv_bfloat162 lp0(__float2bfloat16(v.x - __bfloat162float(h0)),
                           __float2bfloat16(v.y - __bfloat162float(h1)));
        __nv_bfloat162 lp1(__float2bfloat16(v.z - __bfloat162float(h2)),
                           __float2bfloat16(v.w - __bfloat162float(h3)));
        ((__nv_bfloat162*)g_Ahi)[i * 2 + 0] = hp0;
        ((__nv_bfloat162*)g_Ahi)[i * 2 + 1] = hp1;
        ((__nv_bfloat162*)g_Alo)[i * 2 + 0] = lp0;
        ((__nv_bfloat162*)g_Alo)[i * 2 + 1] = lp1;
    }
}

// ============================================================================
// Phase 1 GEMM: C[M,N] = Ahi/lo @ Whi/lo^T + bias  (split bf16, HMMA)
// CTA 128x128, 256 thr (8 warps 2x4, warp tile 64x32), K-chunk 32, 3 stages.
// (R5 configuration — best measured.)
// ============================================================================
#define G1_PITCH   40
#define G1_ARR_B   (128 * G1_PITCH * 2)      // 10240 B per array
#define G1_STAGE_B (4 * G1_ARR_B)            // 40960 B per stage
#define G1_SMEM    (3 * G1_STAGE_B)          // 122880 B

__global__ __launch_bounds__(256, 1) void gemm1_kernel(
    const float* __restrict__ bias, float* __restrict__ C)
{
    extern __shared__ char smem[];
    const uint32_t sb0 = smem_u32(smem);
    const int tid  = threadIdx.x;
    const int wid  = tid >> 5;
    const int lane = tid & 31;
    const int m0 = blockIdx.y * 128;
    const int n0 = blockIdx.x * 128;
    const int warp_m = (wid >> 2) * 64;
    const int warp_n = (wid & 3) * 32;

    float acc[4][4][4];
#pragma unroll
    for (int i = 0; i < 4; i++)
#pragma unroll
        for (int j = 0; j < 4; j++)
#pragma unroll
            for (int k = 0; k < 4; k++) acc[i][j][k] = 0.f;

    const int crow = tid >> 2;       // 0..63
    const int cseg = tid & 3;        // 0..3 (16B units)

    auto issue = [&](int c, int s) {
        const uint32_t st = sb0 + s * G1_STAGE_B;
        const int kb = c * 32 + cseg * 8;
#pragma unroll
        for (int h = 0; h < 2; h++) {
            const int r = crow + h * 64;
            const size_t ga = (size_t)(m0 + r) * NIN + kb;
            const size_t gb = (size_t)(n0 + r) * NIN + kb;
            const uint32_t so = r * 80 + cseg * 16;
            CP16(st + so,                  g_Ahi + ga);
            CP16(st + G1_ARR_B + so,       g_Alo + ga);
            CP16(st + 2 * G1_ARR_B + so,   g_Wxh_hi + gb);
            CP16(st + 3 * G1_ARR_B + so,   g_Wxh_lo + gb);
        }
    };

    issue(0, 0); CP_COMMIT();
    issue(1, 1); CP_COMMIT();

    for (int it = 0; it < 32; it++) {
        CP_WAIT(1);
        __syncthreads();
        if (it + 2 < 32) issue(it + 2, (it + 2) % 3);
        CP_COMMIT();

        const uint32_t st = sb0 + (it % 3) * G1_STAGE_B;
#pragma unroll
        for (int ks = 0; ks < 2; ks++) {
            const uint32_t kb = ks * 32;
            uint32_t ah[4][4], al[4][4];
#pragma unroll
            for (int mt = 0; mt < 4; mt++) {
                const int mr = warp_m + mt * 16 + (lane & 15);
                const uint32_t ad = st + mr * 80 + ((lane >> 4) * 16) + kb;
                ldsm4(ah[mt], ad);
                ldsm4(al[mt], ad + G1_ARR_B);
            }
            uint32_t bh[4][2], bl[4][2];
#pragma unroll
            for (int g = 0; g < 2; g++) {
                const int nr = warp_n + g * 16 + (lane & 7) + ((lane >> 4) << 3);
                const uint32_t bd = st + 2 * G1_ARR_B + nr * 80 +
                                    (((lane >> 3) & 1) * 16) + kb;
                uint32_t t[4];
                ldsm4(t, bd);
                bh[g * 2][0] = t[0]; bh[g * 2][1] = t[1];
                bh[g * 2 + 1][0] = t[2]; bh[g * 2 + 1][1] = t[3];
                ldsm4(t, bd + G1_ARR_B);
                bl[g * 2][0] = t[0]; bl[g * 2][1] = t[1];
                bl[g * 2 + 1][0] = t[2]; bl[g * 2 + 1][1] = t[3];
            }
#pragma unroll
            for (int mt = 0; mt < 4; mt++)
#pragma unroll
                for (int nt = 0; nt < 4; nt++) {
                    mma_bf16(acc[mt][nt], ah[mt], bh[nt]);
                    mma_bf16(acc[mt][nt], ah[mt], bl[nt]);
                    mma_bf16(acc[mt][nt], al[mt], bh[nt]);
                }
        }
    }

#pragma unroll
    for (int mt = 0; mt < 4; mt++) {
        const int m = m0 + warp_m + mt * 16 + (lane >> 2);
#pragma unroll
        for (int nt = 0; nt < 4; nt++) {
            const int n = n0 + warp_n + nt * 8 + (lane & 3) * 2;
            const float b0 = bias[n], b1 = bias[n + 1];
            float2 v0 = make_float2(acc[mt][nt][0] + b0, acc[mt][nt][1] + b1);
            float2 v1 = make_float2(acc[mt][nt][2] + b0, acc[mt][nt][3] + b1);
            *(float2*)(C + (size_t)m * NH + n)       = v0;
            *(float2*)(C + (size_t)(m + 8) * NH + n) = v1;
        }
    }
}

// ============================================================================
// t = 0: h0 = tanh(xw[0]); write fp32 out[0] and bf16 hi/lo state buf 0
// ============================================================================
__global__ __launch_bounds__(256) void tanh0_kernel(float* __restrict__ x)
{
    const size_t i = (size_t)blockIdx.x * blockDim.x + threadIdx.x;  // float4 idx
    float4 v = ((const float4*)x)[i];
    v.x = tanhf(v.x); v.y = tanhf(v.y); v.z = tanhf(v.z); v.w = tanhf(v.w);
    ((float4*)x)[i] = v;
    __nv_bfloat16 h0 = __float2bfloat16(v.x);
    __nv_bfloat16 h1 = __float2bfloat16(v.y);
    __nv_bfloat16 h2 = __float2bfloat16(v.z);
    __nv_bfloat16 h3 = __float2bfloat16(v.w);
    ((__nv_bfloat162*)g_Hhi[0])[i * 2 + 0] = __nv_bfloat162(h0, h1);
    ((__nv_bfloat162*)g_Hhi[0])[i * 2 + 1] = __nv_bfloat162(h2, h3);
    ((__nv_bfloat162*)g_Hlo[0])[i * 2 + 0] =
        __nv_bfloat162(__float2bfloat16(v.x - __bfloat162float(h0)),
                       __float2bfloat16(v.y - __bfloat162float(h1)));
    ((__nv_bfloat162*)g_Hlo[0])[i * 2 + 1] =
        __nv_bfloat162(__float2bfloat16(v.z - __bfloat162float(h2)),
                       __float2bfloat16(v.w - __bfloat162float(h3)));
}

// ============================================================================
// Persistent RNN recurrence: t = 1..511, per-m-group barriers (R5 style).
// 128 CTAs = 4 m-groups (64 rows) x 32 n-blocks (32 cols), 256 threads.
// W_hh hi+lo slice RESIDENT in smem (160 KB); H streamed, K64 chunks, 3 stages.
// SPLIT-K ACROSS WARPS: warps 0-3 do even k16-slices, warps 4-7 odd slices.
// Warp tile 16m x 32n -> 6 ldsm4 per 12 MMAs (was 4 per 6). smem reduction.
// ============================================================================
#define PW_HI    0
#define PW_LO    81920
#define PH_BASE  163840
#define PH_STAGE 20480
#define PH_SUB   5120
#define PH_LO    10240
#define PK_SMEM  225280

__global__ __launch_bounds__(256, 1) void rnn_persist_kernel(float* __restrict__ out)
{
    extern __shared__ char smem[];
    const uint32_t sb = smem_u32(smem);
    const int tid  = threadIdx.x;
    const int wid  = tid >> 5;
    const int lane = tid & 31;
    const int mb = blockIdx.x >> 5;    // 0..3  (m-group)
    const int nb = blockIdx.x & 31;    // 0..31
    const int m0 = mb * 64;
    const int n0 = nb * 32;
    const int warp_m = (wid & 3) * 16;   // 0..48 (both k-halves cover all 64 m)
    const int kh     = wid >> 2;         // 0 = even k16 slices, 1 = odd

    // ---- Load resident W_hh slice (hi+lo), chunked K-major, pitch 80B ----
    for (int idx = tid; idx < 4096; idx += 256) {
        const int ch  = idx >> 7;          // 0..31  k32-chunk
        const int r   = (idx >> 2) & 31;   // 0..31  n-row
        const int seg = idx & 3;           // 0..3   16B seg
        const size_t g = (size_t)(n0 + r) * NH + ch * 32 + seg * 8;
        const uint32_t so = sb + ch * 2560 + r * 80 + seg * 16;
        CP16(so + PW_HI, g_Whh_hi + g);
        CP16(so + PW_LO, g_Whh_lo + g);
    }
    CP_COMMIT(); CP_WAIT(0); __syncthreads();

    const int hrow = tid >> 2;   // 0..63
    const int hseg = tid & 3;

    for (int t = 1; t < T_STEPS; t++) {
        const __nv_bfloat16* Hh = g_Hhi[(t - 1) & 1];
        const __nv_bfloat16* Hl = g_Hlo[(t - 1) & 1];
        __nv_bfloat16* HhO = g_Hhi[t & 1];
        __nv_bfloat16* HlO = g_Hlo[t & 1];
        float* X = out + (size_t)t * BATCH * NH;

        // issue K64 chunk c into stage c%3
        auto issueH = [&](int c) {
            const uint32_t st = sb + PH_BASE + (c % 3) * PH_STAGE +
                                hrow * 80 + hseg * 16;
#pragma unroll
            for (int j = 0; j < 2; j++) {
                const size_t ga = (size_t)(m0 + hrow) * NH + c * 64 + j * 32 + hseg * 8;
                CP16(st + j * PH_SUB,         Hh + ga);
                CP16(st + j * PH_SUB + PH_LO, Hl + ga);
            }
        };
        issueH(0); CP_COMMIT();
        issueH(1); CP_COMMIT();

        // Prefetch this warp's xw tile (needed by reducer warps 0-3 only,
        // but all warps prefetch their warp_m rows; kh=0 warps use it)
        float2 xwr[2][4];
        if (kh == 0) {
            const int mrow = m0 + warp_m + (lane >> 2);
#pragma unroll
            for (int half = 0; half < 2; half++)
#pragma unroll
                for (int nt = 0; nt < 4; nt++) {
                    const int m = mrow + half * 8;
                    const int n = n0 + nt * 8 + (lane & 3) * 2;
                    xwr[half][nt] = *(const float2*)(X + (size_t)m * NH + n);
                }
        }

        float acc[4][4];   // [n8-tile][frag]
#pragma unroll
        for (int i = 0; i < 4; i++)
#pragma unroll
            for (int j = 0; j < 4; j++) acc[i][j] = 0.f;

        for (int it = 0; it < 16; it++) {
            CP_WAIT(1);
            __syncthreads();
            if (it + 2 < 16) issueH(it + 2);
            CP_COMMIT();

            const uint32_t hst = sb + PH_BASE + (it % 3) * PH_STAGE;
#pragma unroll
            for (int j = 0; j < 2; j++) {
                const int slice = 2 * j + kh;        // this warp's k16 slice (0..3)
                const int sub = slice >> 1;
                const uint32_t kb = (slice & 1) * 32;
                uint32_t ah[4], al[4];
                {
                    const uint32_t ad = hst + sub * PH_SUB +
                                        (warp_m + (lane & 15)) * 80 +
                                        ((lane >> 4) * 16) + kb;
                    ldsm4(ah, ad);
                    ldsm4(al, ad + PH_LO);
                }
                uint32_t bh[4][2], bl[4][2];
#pragma unroll
                for (int g = 0; g < 2; g++) {
                    const int nr = g * 16 + (lane & 7) + ((lane >> 4) << 3);
                    const uint32_t bd = sb + (it * 2 + sub) * 2560 + nr * 80 +
                                        (((lane >> 3) & 1) * 16) + kb;
                    uint32_t tmp[4];
                    ldsm4(tmp, bd + PW_HI);
                    bh[g * 2][0] = tmp[0]; bh[g * 2][1] = tmp[1];
                    bh[g * 2 + 1][0] = tmp[2]; bh[g * 2 + 1][1] = tmp[3];
                    ldsm4(tmp, bd + PW_LO);
                    bl[g * 2][0] = tmp[0]; bl[g * 2][1] = tmp[1];
                    bl[g * 2 + 1][0] = tmp[2]; bl[g * 2 + 1][1] = tmp[3];
                }
#pragma unroll
                for (int nt = 0; nt < 4; nt++) mma_bf16(acc[nt], ah, bh[nt]);
#pragma unroll
                for (int nt = 0; nt < 4; nt++) mma_bf16(acc[nt], ah, bl[nt]);
#pragma unroll
                for (int nt = 0; nt < 4; nt++) mma_bf16(acc[nt], al, bh[nt]);
            }
        }

        // ---- Cross-warp split-K reduction via smem (reuse drained H stage) ----
        CP_WAIT(0);
        __syncthreads();
        float* rbuf = (float*)(smem + PH_BASE);   // 64 x 32 fp32 = 8 KB
        if (kh == 1) {
            const int mrow = warp_m + (lane >> 2);
#pragma unroll
            for (int half = 0; half < 2; half++)
#pragma unroll
                for (int nt = 0; nt < 4; nt++) {
                    const int m = mrow + half * 8;
                    const int n = nt * 8 + (lane & 3) * 2;
                    *(float2*)(rbuf + m * 32 + n) =
                        make_float2(acc[nt][half * 2 + 0], acc[nt][half * 2 + 1]);
                }
        }
        __syncthreads();

        // ---- Epilogue (warps 0-3): h = tanh(xw + acc_even + acc_odd) ----
        if (kh == 0) {
            const int mrow = m0 + warp_m + (lane >> 2);
#pragma unroll
            for (int half = 0; half < 2; half++) {
                const int m = mrow + half * 8;
                const int mloc = warp_m + (lane >> 2) + half * 8;
#pragma unroll
                for (int nt = 0; nt < 4; nt++) {
                    const int nloc = nt * 8 + (lane & 3) * 2;
                    const int n = n0 + nloc;
                    const size_t off = (size_t)m * NH + n;
                    const float2 other = *(const float2*)(rbuf + mloc * 32 + nloc);
                    const float s0 = acc[nt][half * 2 + 0] + other.x;
                    const float s1 = acc[nt][half * 2 + 1] + other.y;
                    const float v0 = tanhf(xwr[half][nt].x + s0);
                    const float v1 = tanhf(xwr[half][nt].y + s1);
                    *(float2*)(X + off) = make_float2(v0, v1);
                    const __nv_bfloat16 h0 = __float2bfloat16(v0);
                    const __nv_bfloat16 h1 = __float2bfloat16(v1);
                    *(__nv_bfloat162*)(HhO + off) = __nv_bfloat162(h0, h1);
                    *(__nv_bfloat162*)(HlO + off) = __nv_bfloat162(
                        __float2bfloat16(v0 - __bfloat162float(h0)),
                        __float2bfloat16(v1 - __bfloat162float(h1)));
                    if (t == T_STEPS - 1)
                        *(float2*)(out + (size_t)T_STEPS * BATCH * NH + off) =
                            make_float2(v0, v1);
                }
            }
        }

        // ---- Per-m-group barrier between steps (32 CTAs) ----
        __syncthreads();
        if (tid == 0) grid_bar(mb);
        __syncthreads();
    }
}

// ============================================================================
// Launch
// ============================================================================
extern "C" void kernel_launch(void* const* d_in, const int* in_sizes, int n_in,
                              void* d_out, int out_size)
{
    const float* inputs = (const float*)d_in[0];   // [T, B, NIN]
    const float* W_xh   = (const float*)d_in[1];   // [NIN, NH]
    const float* W_hh   = (const float*)d_in[2];   // [NH, NH]
    const float* b_h    = (const float*)d_in[3];   // [NH]
    float* out = (float*)d_out;                    // [T, B, NH] + [B, NH]

    const size_t step_elems = (size_t)BATCH * NH;  // 262144

    static bool attr_set = false;
    if (!attr_set) {
        cudaFuncSetAttribute(gemm1_kernel,
                             cudaFuncAttributeMaxDynamicSharedMemorySize, G1_SMEM);
        cudaFuncSetAttribute(rnn_persist_kernel,
                             cudaFuncAttributeMaxDynamicSharedMemorySize, PK_SMEM);
        attr_set = true;
    }

    // Prep: split weights (transposed) and inputs into bf16 hi/lo
    {
        dim3 grid(NH / 32, NIN / 32);
        split_w_kernel<<<grid, 256>>>(W_xh, 0);
        split_w_kernel<<<grid, 256>>>(W_hh, 1);
        split_a_kernel<<<8192, 256>>>(inputs);
    }

    // Phase 1: xw = inputs @ W_xh + b_h  -> out[0..T)
    {
        dim3 grid(NH / 128, M_TOTAL / 128);   // (8, 1024)
        gemm1_kernel<<<grid, 256, G1_SMEM>>>(b_h, out);
    }

    // t = 0
    tanh0_kernel<<<(int)(step_elems / 4 / 256), 256>>>(out);

    // t = 1..T-1 in ONE persistent kernel (also writes final_state tail)
    rnn_persist_kernel<<<PK_CTAS, 256, PK_SMEM>>>(out);
}

// round 9
// speedup vs baseline: 1.9942x; 1.1355x over previous
#include <cuda_runtime.h>
#include <cuda_bf16.h>
#include <cuda_fp16.h>
#include <math.h>
#include <stdint.h>

// Problem shapes (fixed by reference)
#define T_STEPS 512
#define BATCH   256
#define NIN     1024
#define NH      1024
#define M_TOTAL (T_STEPS * BATCH)   // 131072

// ============================================================================
// Device scratch (static — no allocation allowed)
// ============================================================================
__device__ __nv_bfloat16 g_Ahi[(size_t)M_TOTAL * NIN];   // inputs hi, [M][K]
__device__ __nv_bfloat16 g_Alo[(size_t)M_TOTAL * NIN];   // inputs lo
__device__ __nv_bfloat16 g_Wxh_hi[(size_t)NH * NIN];     // W_xh^T hi, [N][K]
__device__ __nv_bfloat16 g_Wxh_lo[(size_t)NH * NIN];
__device__ __half g_Whh16_hi[(size_t)NH * NH];           // W_hh^T fp16 hi, [N][K]
__device__ __half g_Whh16_lo[(size_t)NH * NH];           // fp16 lo, PRE-SCALED x2048
__device__ __half g_H16[2][(size_t)BATCH * NH];          // state fp16, double buffered

// Per-m-group barrier state (4 groups of 32 CTAs); zero-init, phase monotonic
__device__ unsigned g_bar_count[4];
__device__ unsigned g_bar_phase[4];

// ============================================================================
// PTX helpers (all sm_80-era: compile for plain compute_103)
// ============================================================================
__device__ __forceinline__ uint32_t smem_u32(const void* p) {
    uint32_t a;
    asm("{ .reg .u64 t; cvta.to.shared.u64 t, %1; cvt.u32.u64 %0, t; }"
        : "=r"(a) : "l"(p));
    return a;
}

#define CP16(dst, src) \
    asm volatile("cp.async.cg.shared.global [%0], [%1], 16;" :: "r"(dst), "l"(src))
#define CP_COMMIT() asm volatile("cp.async.commit_group;" ::: "memory")
#define CP_WAIT(n)  asm volatile("cp.async.wait_group %0;" :: "n"(n) : "memory")

__device__ __forceinline__ void ldsm4(uint32_t r[4], uint32_t addr) {
    asm volatile("ldmatrix.sync.aligned.m8n8.x4.shared.b16 {%0,%1,%2,%3}, [%4];"
                 : "=r"(r[0]), "=r"(r[1]), "=r"(r[2]), "=r"(r[3]) : "r"(addr));
}

__device__ __forceinline__ void mma_bf16(float c[4], const uint32_t a[4],
                                         const uint32_t b[2]) {
    asm volatile(
        "mma.sync.aligned.m16n8k16.row.col.f32.bf16.bf16.f32 "
        "{%0,%1,%2,%3}, {%4,%5,%6,%7}, {%8,%9}, {%0,%1,%2,%3};"
        : "+f"(c[0]), "+f"(c[1]), "+f"(c[2]), "+f"(c[3])
        : "r"(a[0]), "r"(a[1]), "r"(a[2]), "r"(a[3]), "r"(b[0]), "r"(b[1]));
}

__device__ __forceinline__ void mma_f16(float c[4], const uint32_t a[4],
                                        const uint32_t b[2]) {
    asm volatile(
        "mma.sync.aligned.m16n8k16.row.col.f32.f16.f16.f32 "
        "{%0,%1,%2,%3}, {%4,%5,%6,%7}, {%8,%9}, {%0,%1,%2,%3};"
        : "+f"(c[0]), "+f"(c[1]), "+f"(c[2]), "+f"(c[3])
        : "r"(a[0]), "r"(a[1]), "r"(a[2]), "r"(a[3]), "r"(b[0]), "r"(b[1]));
}

__device__ __forceinline__ unsigned ld_acq(const unsigned* p) {
    unsigned v;
    asm volatile("ld.acquire.gpu.global.u32 %0, [%1];" : "=r"(v) : "l"(p) : "memory");
    return v;
}
__device__ __forceinline__ void st_rel(unsigned* p, unsigned v) {
    asm volatile("st.release.gpu.global.u32 [%0], %1;" :: "l"(p), "r"(v) : "memory");
}

#define PK_CTAS  128
#define PK_GROUP 32   // CTAs per m-group barrier

__device__ __forceinline__ void grid_bar(int g) {
    unsigned ph = ld_acq(&g_bar_phase[g]);
    __threadfence();
    unsigned old = atomicAdd(&g_bar_count[g], 1);
    if (old == PK_GROUP - 1) {
        g_bar_count[g] = 0;
        st_rel(&g_bar_phase[g], ph + 1);
    } else {
        while (ld_acq(&g_bar_phase[g]) == ph) { }
    }
}

// ============================================================================
// Prep: split + transpose W_xh [K][N] fp32 -> [N][K] bf16 hi/lo (for gemm1)
// ============================================================================
__global__ __launch_bounds__(256) void split_w_kernel(const float* __restrict__ W)
{
    __shared__ float tile[32][33];
    const int bx = blockIdx.x * 32;   // n block
    const int by = blockIdx.y * 32;   // k block
    const int tx = threadIdx.x & 31;
    const int ty = threadIdx.x >> 5;
    for (int i = ty; i < 32; i += 8)
        tile[i][tx] = W[(size_t)(by + i) * NH + bx + tx];
    __syncthreads();
    for (int i = ty; i < 32; i += 8) {
        float x = tile[tx][i];                 // W[by+tx][bx+i]
        __nv_bfloat16 h = __float2bfloat16(x);
        __nv_bfloat16 l = __float2bfloat16(x - __bfloat162float(h));
        size_t o = (size_t)(bx + i) * NIN + by + tx;
        g_Wxh_hi[o] = h;
        g_Wxh_lo[o] = l;
    }
}

// ============================================================================
// Prep: split + transpose W_hh [K][N] fp32 -> [N][K] fp16 hi + lo(x2048)
// ============================================================================
__global__ __launch_bounds__(256) void split_whh_kernel(const float* __restrict__ W)
{
    __shared__ float tile[32][33];
    const int bx = blockIdx.x * 32;   // n block
    const int by = blockIdx.y * 32;   // k block
    const int tx = threadIdx.x & 31;
    const int ty = threadIdx.x >> 5;
    for (int i = ty; i < 32; i += 8)
        tile[i][tx] = W[(size_t)(by + i) * NH + bx + tx];
    __syncthreads();
    for (int i = ty; i < 32; i += 8) {
        float x = tile[tx][i];                 // W[by+tx][bx+i]
        __half h = __float2half(x);
        __half l = __float2half((x - __half2float(h)) * 2048.0f);
        size_t o = (size_t)(bx + i) * NH + by + tx;
        g_Whh16_hi[o] = h;
        g_Whh16_lo[o] = l;
    }
}

// ============================================================================
// Prep: split inputs fp32 [M][K] -> g_Ahi/g_Alo bf16 (same layout)
// ============================================================================
__global__ __launch_bounds__(256) void split_a_kernel(const float* __restrict__ A)
{
    const size_t n4 = (size_t)M_TOTAL * NIN / 4;
    size_t i = (size_t)blockIdx.x * blockDim.x + threadIdx.x;
    const size_t stride = (size_t)gridDim.x * blockDim.x;
    for (; i < n4; i += stride) {
        float4 v = ((const float4*)A)[i];
        __nv_bfloat16 h0 = __float2bfloat16(v.x);
        __nv_bfloat16 h1 = __float2bfloat16(v.y);
        __nv_bfloat16 h2 = __float2bfloat16(v.z);
        __nv_bfloat16 h3 = __float2bfloat16(v.w);
        __nv_bfloat162 hp0(h0, h1), hp1(h2, h3);
        __nv_bfloat162 lp0(__float2bfloat16(v.x - __bfloat162float(h0)),
                           __float2bfloat16(v.y - __bfloat162float(h1)));
        __nv_bfloat162 lp1(__float2bfloat16(v.z - __bfloat162float(h2)),
                           __float2bfloat16(v.w - __bfloat162float(h3)));
        ((__nv_bfloat162*)g_Ahi)[i * 2 + 0] = hp0;
        ((__nv_bfloat162*)g_Ahi)[i * 2 + 1] = hp1;
        ((__nv_bfloat162*)g_Alo)[i * 2 + 0] = lp0;
        ((__nv_bfloat162*)g_Alo)[i * 2 + 1] = lp1;
    }
}

// ============================================================================
// Phase 1 GEMM: C[M,N] = Ahi/lo @ Whi/lo^T + bias  (split bf16, HMMA)
// CTA 128x128, 256 thr (8 warps 2x4, warp tile 64x32), K-chunk 32, 3 stages.
// (R5 configuration — best measured.)
// ============================================================================
#define G1_PITCH   40
#define G1_ARR_B   (128 * G1_PITCH * 2)      // 10240 B per array
#define G1_STAGE_B (4 * G1_ARR_B)            // 40960 B per stage
#define G1_SMEM    (3 * G1_STAGE_B)          // 122880 B

__global__ __launch_bounds__(256, 1) void gemm1_kernel(
    const float* __restrict__ bias, float* __restrict__ C)
{
    extern __shared__ char smem[];
    const uint32_t sb0 = smem_u32(smem);
    const int tid  = threadIdx.x;
    const int wid  = tid >> 5;
    const int lane = tid & 31;
    const int m0 = blockIdx.y * 128;
    const int n0 = blockIdx.x * 128;
    const int warp_m = (wid >> 2) * 64;
    const int warp_n = (wid & 3) * 32;

    float acc[4][4][4];
#pragma unroll
    for (int i = 0; i < 4; i++)
#pragma unroll
        for (int j = 0; j < 4; j++)
#pragma unroll
            for (int k = 0; k < 4; k++) acc[i][j][k] = 0.f;

    const int crow = tid >> 2;       // 0..63
    const int cseg = tid & 3;        // 0..3 (16B units)

    auto issue = [&](int c, int s) {
        const uint32_t st = sb0 + s * G1_STAGE_B;
        const int kb = c * 32 + cseg * 8;
#pragma unroll
        for (int h = 0; h < 2; h++) {
            const int r = crow + h * 64;
            const size_t ga = (size_t)(m0 + r) * NIN + kb;
            const size_t gb = (size_t)(n0 + r) * NIN + kb;
            const uint32_t so = r * 80 + cseg * 16;
            CP16(st + so,                  g_Ahi + ga);
            CP16(st + G1_ARR_B + so,       g_Alo + ga);
            CP16(st + 2 * G1_ARR_B + so,   g_Wxh_hi + gb);
            CP16(st + 3 * G1_ARR_B + so,   g_Wxh_lo + gb);
        }
    };

    issue(0, 0); CP_COMMIT();
    issue(1, 1); CP_COMMIT();

    for (int it = 0; it < 32; it++) {
        CP_WAIT(1);
        __syncthreads();
        if (it + 2 < 32) issue(it + 2, (it + 2) % 3);
        CP_COMMIT();

        const uint32_t st = sb0 + (it % 3) * G1_STAGE_B;
#pragma unroll
        for (int ks = 0; ks < 2; ks++) {
            const uint32_t kb = ks * 32;
            uint32_t ah[4][4], al[4][4];
#pragma unroll
            for (int mt = 0; mt < 4; mt++) {
                const int mr = warp_m + mt * 16 + (lane & 15);
                const uint32_t ad = st + mr * 80 + ((lane >> 4) * 16) + kb;
                ldsm4(ah[mt], ad);
                ldsm4(al[mt], ad + G1_ARR_B);
            }
            uint32_t bh[4][2], bl[4][2];
#pragma unroll
            for (int g = 0; g < 2; g++) {
                const int nr = warp_n + g * 16 + (lane & 7) + ((lane >> 4) << 3);
                const uint32_t bd = st + 2 * G1_ARR_B + nr * 80 +
                                    (((lane >> 3) & 1) * 16) + kb;
                uint32_t t[4];
                ldsm4(t, bd);
                bh[g * 2][0] = t[0]; bh[g * 2][1] = t[1];
                bh[g * 2 + 1][0] = t[2]; bh[g * 2 + 1][1] = t[3];
                ldsm4(t, bd + G1_ARR_B);
                bl[g * 2][0] = t[0]; bl[g * 2][1] = t[1];
                bl[g * 2 + 1][0] = t[2]; bl[g * 2 + 1][1] = t[3];
            }
#pragma unroll
            for (int mt = 0; mt < 4; mt++)
#pragma unroll
                for (int nt = 0; nt < 4; nt++) {
                    mma_bf16(acc[mt][nt], ah[mt], bh[nt]);
                    mma_bf16(acc[mt][nt], ah[mt], bl[nt]);
                    mma_bf16(acc[mt][nt], al[mt], bh[nt]);
                }
        }
    }

#pragma unroll
    for (int mt = 0; mt < 4; mt++) {
        const int m = m0 + warp_m + mt * 16 + (lane >> 2);
#pragma unroll
        for (int nt = 0; nt < 4; nt++) {
            const int n = n0 + warp_n + nt * 8 + (lane & 3) * 2;
            const float b0 = bias[n], b1 = bias[n + 1];
            float2 v0 = make_float2(acc[mt][nt][0] + b0, acc[mt][nt][1] + b1);
            float2 v1 = make_float2(acc[mt][nt][2] + b0, acc[mt][nt][3] + b1);
            *(float2*)(C + (size_t)m * NH + n)       = v0;
            *(float2*)(C + (size_t)(m + 8) * NH + n) = v1;
        }
    }
}

// ============================================================================
// t = 0: h0 = tanh(xw[0]); write fp32 out[0] and fp16 state buf 0
// ============================================================================
__global__ __launch_bounds__(256) void tanh0_kernel(float* __restrict__ x)
{
    const size_t i = (size_t)blockIdx.x * blockDim.x + threadIdx.x;  // float4 idx
    float4 v = ((const float4*)x)[i];
    v.x = tanhf(v.x); v.y = tanhf(v.y); v.z = tanhf(v.z); v.w = tanhf(v.w);
    ((float4*)x)[i] = v;
    ((__half2*)g_H16[0])[i * 2 + 0] = __floats2half2_rn(v.x, v.y);
    ((__half2*)g_H16[0])[i * 2 + 1] = __floats2half2_rn(v.z, v.w);
}

// ============================================================================
// Persistent RNN recurrence: t = 1..511, per-m-group barriers.
// 128 CTAs = 4 m-groups (64 rows) x 32 n-blocks (32 cols), 256 threads.
// W_hh fp16 hi+lo(x2048) slice RESIDENT in smem (160 KB).
// H (single fp16) streamed: K64 chunks, 3 stages x 10 KB, 16 iters/step.
// Split-K across warps: warps 0-3 even k16-slices, 4-7 odd. 2-term MMA:
//   acc_h += Hhi*Whi ; acc_l += Hhi*(Wlo*2048) ; h = tanh(xw + acc_h + acc_l/2048)
// ============================================================================
#define PW_HI    0
#define PW_LO    81920
#define PH_BASE  163840
#define PH_STAGE 10240
#define PH_SUB   5120
#define PK_SMEM  194560
#define LO_SCALE 4.8828125e-4f   // 1/2048, exact

__global__ __launch_bounds__(256, 1) void rnn_persist_kernel(float* __restrict__ out)
{
    extern __shared__ char smem[];
    const uint32_t sb = smem_u32(smem);
    const int tid  = threadIdx.x;
    const int wid  = tid >> 5;
    const int lane = tid & 31;
    const int mb = blockIdx.x >> 5;    // 0..3  (m-group)
    const int nb = blockIdx.x & 31;    // 0..31
    const int m0 = mb * 64;
    const int n0 = nb * 32;
    const int warp_m = (wid & 3) * 16;   // 0..48
    const int kh     = wid >> 2;         // 0 = even k16 slices, 1 = odd

    // ---- Load resident W_hh fp16 slice (hi + scaled lo), pitch 80B ----
    for (int idx = tid; idx < 4096; idx += 256) {
        const int ch  = idx >> 7;          // 0..31  k32-chunk
        const int r   = (idx >> 2) & 31;   // 0..31  n-row
        const int seg = idx & 3;           // 0..3   16B seg
        const size_t g = (size_t)(n0 + r) * NH + ch * 32 + seg * 8;
        const uint32_t so = sb + ch * 2560 + r * 80 + seg * 16;
        CP16(so + PW_HI, g_Whh16_hi + g);
        CP16(so + PW_LO, g_Whh16_lo + g);
    }
    CP_COMMIT(); CP_WAIT(0); __syncthreads();

    const int hrow = tid >> 2;   // 0..63
    const int hseg = tid & 3;

    for (int t = 1; t < T_STEPS; t++) {
        const __half* Hh = g_H16[(t - 1) & 1];
        __half* HO = g_H16[t & 1];
        float* X = out + (size_t)t * BATCH * NH;

        // issue K64 chunk c into stage c%3 (hi only: 2 x CP16 per thread)
        auto issueH = [&](int c) {
            const uint32_t st = sb + PH_BASE + (c % 3) * PH_STAGE +
                                hrow * 80 + hseg * 16;
#pragma unroll
            for (int j = 0; j < 2; j++) {
                const size_t ga = (size_t)(m0 + hrow) * NH + c * 64 + j * 32 + hseg * 8;
                CP16(st + j * PH_SUB, Hh + ga);
            }
        };
        issueH(0); CP_COMMIT();
        issueH(1); CP_COMMIT();

        // Prefetch xw tile (used by kh=0 warps in the epilogue)
        float2 xwr[2][4];
        if (kh == 0) {
            const int mrow = m0 + warp_m + (lane >> 2);
#pragma unroll
            for (int half = 0; half < 2; half++)
#pragma unroll
                for (int nt = 0; nt < 4; nt++) {
                    const int m = mrow + half * 8;
                    const int n = n0 + nt * 8 + (lane & 3) * 2;
                    xwr[half][nt] = *(const float2*)(X + (size_t)m * NH + n);
                }
        }

        float acch[4][4], accl[4][4];
#pragma unroll
        for (int i = 0; i < 4; i++)
#pragma unroll
            for (int j = 0; j < 4; j++) { acch[i][j] = 0.f; accl[i][j] = 0.f; }

        for (int it = 0; it < 16; it++) {
            CP_WAIT(1);
            __syncthreads();
            if (it + 2 < 16) issueH(it + 2);
            CP_COMMIT();

            const uint32_t hst = sb + PH_BASE + (it % 3) * PH_STAGE;
#pragma unroll
            for (int j = 0; j < 2; j++) {
                const int slice = 2 * j + kh;        // this warp's k16 slice (0..3)
                const int sub = slice >> 1;
                const uint32_t kb = (slice & 1) * 32;
                uint32_t ah[4];
                {
                    const uint32_t ad = hst + sub * PH_SUB +
                                        (warp_m + (lane & 15)) * 80 +
                                        ((lane >> 4) * 16) + kb;
                    ldsm4(ah, ad);
                }
                uint32_t bh[4][2], bl[4][2];
#pragma unroll
                for (int g = 0; g < 2; g++) {
                    const int nr = g * 16 + (lane & 7) + ((lane >> 4) << 3);
                    const uint32_t bd = sb + (it * 2 + sub) * 2560 + nr * 80 +
                                        (((lane >> 3) & 1) * 16) + kb;
                    uint32_t tmp[4];
                    ldsm4(tmp, bd + PW_HI);
                    bh[g * 2][0] = tmp[0]; bh[g * 2][1] = tmp[1];
                    bh[g * 2 + 1][0] = tmp[2]; bh[g * 2 + 1][1] = tmp[3];
                    ldsm4(tmp, bd + PW_LO);
                    bl[g * 2][0] = tmp[0]; bl[g * 2][1] = tmp[1];
                    bl[g * 2 + 1][0] = tmp[2]; bl[g * 2 + 1][1] = tmp[3];
                }
#pragma unroll
                for (int nt = 0; nt < 4; nt++) mma_f16(acch[nt], ah, bh[nt]);
#pragma unroll
                for (int nt = 0; nt < 4; nt++) mma_f16(accl[nt], ah, bl[nt]);
            }
        }

        // ---- Cross-warp split-K reduction via smem (reuse drained H stage) ----
        CP_WAIT(0);
        __syncthreads();
        float* rbuf = (float*)(smem + PH_BASE);   // 64 x 32 fp32 = 8 KB
        if (kh == 1) {
            const int mrow = warp_m + (lane >> 2);
#pragma unroll
            for (int half = 0; half < 2; half++)
#pragma unroll
                for (int nt = 0; nt < 4; nt++) {
                    const int m = mrow + half * 8;
                    const int n = nt * 8 + (lane & 3) * 2;
                    *(float2*)(rbuf + m * 32 + n) = make_float2(
                        acch[nt][half * 2 + 0] + accl[nt][half * 2 + 0] * LO_SCALE,
                        acch[nt][half * 2 + 1] + accl[nt][half * 2 + 1] * LO_SCALE);
                }
        }
        __syncthreads();

        // ---- Epilogue (warps 0-3): h = tanh(xw + self + other) ----
        if (kh == 0) {
            const int mrow = m0 + warp_m + (lane >> 2);
#pragma unroll
            for (int half = 0; half < 2; half++) {
                const int m = mrow + half * 8;
                const int mloc = warp_m + (lane >> 2) + half * 8;
#pragma unroll
                for (int nt = 0; nt < 4; nt++) {
                    const int nloc = nt * 8 + (lane & 3) * 2;
                    const int n = n0 + nloc;
                    const size_t off = (size_t)m * NH + n;
                    const float2 other = *(const float2*)(rbuf + mloc * 32 + nloc);
                    const float s0 = acch[nt][half * 2 + 0] +
                                     accl[nt][half * 2 + 0] * LO_SCALE + other.x;
                    const float s1 = acch[nt][half * 2 + 1] +
                                     accl[nt][half * 2 + 1] * LO_SCALE + other.y;
                    const float v0 = tanhf(xwr[half][nt].x + s0);
                    const float v1 = tanhf(xwr[half][nt].y + s1);
                    *(float2*)(X + off) = make_float2(v0, v1);
                    *(__half2*)(HO + off) = __floats2half2_rn(v0, v1);
                    if (t == T_STEPS - 1)
                        *(float2*)(out + (size_t)T_STEPS * BATCH * NH + off) =
                            make_float2(v0, v1);
                }
            }
        }

        // ---- Per-m-group barrier between steps (32 CTAs) ----
        __syncthreads();
        if (tid == 0) grid_bar(mb);
        __syncthreads();
    }
}

// ============================================================================
// Launch
// ============================================================================
extern "C" void kernel_launch(void* const* d_in, const int* in_sizes, int n_in,
                              void* d_out, int out_size)
{
    const float* inputs = (const float*)d_in[0];   // [T, B, NIN]
    const float* W_xh   = (const float*)d_in[1];   // [NIN, NH]
    const float* W_hh   = (const float*)d_in[2];   // [NH, NH]
    const float* b_h    = (const float*)d_in[3];   // [NH]
    float* out = (float*)d_out;                    // [T, B, NH] + [B, NH]

    const size_t step_elems = (size_t)BATCH * NH;  // 262144

    static bool attr_set = false;
    if (!attr_set) {
        cudaFuncSetAttribute(gemm1_kernel,
                             cudaFuncAttributeMaxDynamicSharedMemorySize, G1_SMEM);
        cudaFuncSetAttribute(rnn_persist_kernel,
                             cudaFuncAttributeMaxDynamicSharedMemorySize, PK_SMEM);
        attr_set = true;
    }

    // Prep: split weights (transposed) and inputs
    {
        dim3 grid(NH / 32, NIN / 32);
        split_w_kernel<<<grid, 256>>>(W_xh);
        split_whh_kernel<<<grid, 256>>>(W_hh);
        split_a_kernel<<<8192, 256>>>(inputs);
    }

    // Phase 1: xw = inputs @ W_xh + b_h  -> out[0..T)
    {
        dim3 grid(NH / 128, M_TOTAL / 128);   // (8, 1024)
        gemm1_kernel<<<grid, 256, G1_SMEM>>>(b_h, out);
    }

    // t = 0
    tanh0_kernel<<<(int)(step_elems / 4 / 256), 256>>>(out);

    // t = 1..T-1 in ONE persistent kernel (also writes final_state tail)
    rnn_persist_kernel<<<PK_CTAS, 256, PK_SMEM>>>(out);
}

// round 10
// speedup vs baseline: 2.1800x; 1.0932x over previous
#include <cuda_runtime.h>
#include <cuda_bf16.h>
#include <cuda_fp16.h>
#include <math.h>
#include <stdint.h>

// Problem shapes (fixed by reference)
#define T_STEPS 512
#define BATCH   256
#define NIN     1024
#define NH      1024
#define M_TOTAL (T_STEPS * BATCH)   // 131072

// ============================================================================
// Device scratch (static — no allocation allowed)
// ============================================================================
__device__ __half g_A16[(size_t)M_TOTAL * NIN];          // inputs fp16, [M][K]
__device__ __half g_Wxh16_hi[(size_t)NH * NIN];          // W_xh^T fp16 hi, [N][K]
__device__ __half g_Wxh16_lo[(size_t)NH * NIN];          // fp16 lo, PRE-SCALED x2048
__device__ __half g_Whh16_hi[(size_t)NH * NH];           // W_hh^T fp16 hi, [N][K]
__device__ __half g_Whh16_lo[(size_t)NH * NH];           // fp16 lo, PRE-SCALED x2048
__device__ __half g_H16[2][(size_t)BATCH * NH];          // state fp16, double buffered

// Per-m-group barrier state (4 groups of 32 CTAs); zero-init, phase monotonic
__device__ unsigned g_bar_count[4];
__device__ unsigned g_bar_phase[4];

#define LO_SCALE 4.8828125e-4f   // 1/2048, exact

// ============================================================================
// PTX helpers (all sm_80-era: compile for plain compute_103)
// ============================================================================
__device__ __forceinline__ uint32_t smem_u32(const void* p) {
    uint32_t a;
    asm("{ .reg .u64 t; cvta.to.shared.u64 t, %1; cvt.u32.u64 %0, t; }"
        : "=r"(a) : "l"(p));
    return a;
}

#define CP16(dst, src) \
    asm volatile("cp.async.cg.shared.global [%0], [%1], 16;" :: "r"(dst), "l"(src))
#define CP_COMMIT() asm volatile("cp.async.commit_group;" ::: "memory")
#define CP_WAIT(n)  asm volatile("cp.async.wait_group %0;" :: "n"(n) : "memory")

__device__ __forceinline__ void ldsm4(uint32_t r[4], uint32_t addr) {
    asm volatile("ldmatrix.sync.aligned.m8n8.x4.shared.b16 {%0,%1,%2,%3}, [%4];"
                 : "=r"(r[0]), "=r"(r[1]), "=r"(r[2]), "=r"(r[3]) : "r"(addr));
}

__device__ __forceinline__ void mma_f16(float c[4], const uint32_t a[4],
                                        const uint32_t b[2]) {
    asm volatile(
        "mma.sync.aligned.m16n8k16.row.col.f32.f16.f16.f32 "
        "{%0,%1,%2,%3}, {%4,%5,%6,%7}, {%8,%9}, {%0,%1,%2,%3};"
        : "+f"(c[0]), "+f"(c[1]), "+f"(c[2]), "+f"(c[3])
        : "r"(a[0]), "r"(a[1]), "r"(a[2]), "r"(a[3]), "r"(b[0]), "r"(b[1]));
}

__device__ __forceinline__ unsigned ld_acq(const unsigned* p) {
    unsigned v;
    asm volatile("ld.acquire.gpu.global.u32 %0, [%1];" : "=r"(v) : "l"(p) : "memory");
    return v;
}
__device__ __forceinline__ void st_rel(unsigned* p, unsigned v) {
    asm volatile("st.release.gpu.global.u32 [%0], %1;" :: "l"(p), "r"(v) : "memory");
}

#define PK_CTAS  128
#define PK_GROUP 32   // CTAs per m-group barrier

__device__ __forceinline__ void grid_bar(int g) {
    unsigned ph = ld_acq(&g_bar_phase[g]);
    __threadfence();
    unsigned old = atomicAdd(&g_bar_count[g], 1);
    if (old == PK_GROUP - 1) {
        g_bar_count[g] = 0;
        st_rel(&g_bar_phase[g], ph + 1);
    } else {
        while (ld_acq(&g_bar_phase[g]) == ph) { }
    }
}

// ============================================================================
// Prep: split + transpose a weight [K][N] fp32 -> [N][K] fp16 hi + lo(x2048)
// which = 0 -> W_xh arrays (K=NIN), 1 -> W_hh arrays (K=NH)
// ============================================================================
__global__ __launch_bounds__(256) void split_w16_kernel(const float* __restrict__ W,
                                                        int which)
{
    __shared__ float tile[32][33];
    __half* hiOut = which ? g_Whh16_hi : g_Wxh16_hi;
    __half* loOut = which ? g_Whh16_lo : g_Wxh16_lo;
    const int bx = blockIdx.x * 32;   // n block
    const int by = blockIdx.y * 32;   // k block
    const int tx = threadIdx.x & 31;
    const int ty = threadIdx.x >> 5;
    for (int i = ty; i < 32; i += 8)
        tile[i][tx] = W[(size_t)(by + i) * NH + bx + tx];
    __syncthreads();
    for (int i = ty; i < 32; i += 8) {
        float x = tile[tx][i];                 // W[by+tx][bx+i]
        __half h = __float2half(x);
        __half l = __float2half((x - __half2float(h)) * 2048.0f);
        size_t o = (size_t)(bx + i) * NIN + by + tx;
        hiOut[o] = h;
        loOut[o] = l;
    }
}

// ============================================================================
// Prep: inputs fp32 [M][K] -> g_A16 fp16 (same layout)
// ============================================================================
__global__ __launch_bounds__(256) void conv_a_kernel(const float* __restrict__ A)
{
    const size_t n4 = (size_t)M_TOTAL * NIN / 4;
    size_t i = (size_t)blockIdx.x * blockDim.x + threadIdx.x;
    const size_t stride = (size_t)gridDim.x * blockDim.x;
    for (; i < n4; i += stride) {
        float4 v = ((const float4*)A)[i];
        ((__half2*)g_A16)[i * 2 + 0] = __floats2half2_rn(v.x, v.y);
        ((__half2*)g_A16)[i * 2 + 1] = __floats2half2_rn(v.z, v.w);
    }
}

// ============================================================================
// Phase 1 GEMM: C[M,N] = A16 @ (Whi + Wlo/2048)^T + bias  (fp16 2-term, HMMA)
// CTA 128x128, 512 thr (16 warps 4x4, warp tile 32x32), K-chunk 32, 3 stages.
// smem stage: A16[128][80B] | Whi[128][80B] | Wlo[128][80B]
// ============================================================================
#define G1_ARR_B   (128 * 80)                // 10240 B per array
#define G1_STAGE_B (3 * G1_ARR_B)            // 30720 B per stage
#define G1_SMEM    (3 * G1_STAGE_B)          // 92160 B

__global__ __launch_bounds__(512, 1) void gemm1_kernel(
    const float* __restrict__ bias, float* __restrict__ C)
{
    extern __shared__ char smem[];
    const uint32_t sb0 = smem_u32(smem);
    const int tid  = threadIdx.x;
    const int wid  = tid >> 5;
    const int lane = tid & 31;
    const int m0 = blockIdx.y * 128;
    const int n0 = blockIdx.x * 128;
    const int warp_m = (wid >> 2) * 32;
    const int warp_n = (wid & 3) * 32;

    float acch[2][4][4], accl[2][4][4];
#pragma unroll
    for (int i = 0; i < 2; i++)
#pragma unroll
        for (int j = 0; j < 4; j++)
#pragma unroll
            for (int k = 0; k < 4; k++) { acch[i][j][k] = 0.f; accl[i][j][k] = 0.f; }

    const int crow = tid >> 2;       // 0..127
    const int cseg = tid & 3;        // 0..3 (16B units)

    auto issue = [&](int c, int s) {
        const uint32_t st = sb0 + s * G1_STAGE_B;
        const int kb = c * 32 + cseg * 8;
        const uint32_t so = crow * 80 + cseg * 16;
        const size_t ga = (size_t)(m0 + crow) * NIN + kb;
        const size_t gb = (size_t)(n0 + crow) * NIN + kb;
        CP16(st + so,                g_A16 + ga);
        CP16(st + G1_ARR_B + so,     g_Wxh16_hi + gb);
        CP16(st + 2 * G1_ARR_B + so, g_Wxh16_lo + gb);
    };

    issue(0, 0); CP_COMMIT();
    issue(1, 1); CP_COMMIT();

    for (int it = 0; it < 32; it++) {
        CP_WAIT(1);
        __syncthreads();
        if (it + 2 < 32) issue(it + 2, (it + 2) % 3);
        CP_COMMIT();

        const uint32_t st = sb0 + (it % 3) * G1_STAGE_B;
#pragma unroll
        for (int ks = 0; ks < 2; ks++) {
            const uint32_t kb = ks * 32;
            uint32_t ah[2][4];
#pragma unroll
            for (int mt = 0; mt < 2; mt++) {
                const int mr = warp_m + mt * 16 + (lane & 15);
                const uint32_t ad = st + mr * 80 + ((lane >> 4) * 16) + kb;
                ldsm4(ah[mt], ad);
            }
            uint32_t bh[4][2], bl[4][2];
#pragma unroll
            for (int g = 0; g < 2; g++) {
                const int nr = warp_n + g * 16 + (lane & 7) + ((lane >> 4) << 3);
                const uint32_t bd = st + G1_ARR_B + nr * 80 +
                                    (((lane >> 3) & 1) * 16) + kb;
                uint32_t t[4];
                ldsm4(t, bd);
                bh[g * 2][0] = t[0]; bh[g * 2][1] = t[1];
                bh[g * 2 + 1][0] = t[2]; bh[g * 2 + 1][1] = t[3];
                ldsm4(t, bd + G1_ARR_B);
                bl[g * 2][0] = t[0]; bl[g * 2][1] = t[1];
                bl[g * 2 + 1][0] = t[2]; bl[g * 2 + 1][1] = t[3];
            }
#pragma unroll
            for (int mt = 0; mt < 2; mt++)
#pragma unroll
                for (int nt = 0; nt < 4; nt++)
                    mma_f16(acch[mt][nt], ah[mt], bh[nt]);
#pragma unroll
            for (int mt = 0; mt < 2; mt++)
#pragma unroll
                for (int nt = 0; nt < 4; nt++)
                    mma_f16(accl[mt][nt], ah[mt], bl[nt]);
        }
    }

#pragma unroll
    for (int mt = 0; mt < 2; mt++) {
        const int m = m0 + warp_m + mt * 16 + (lane >> 2);
#pragma unroll
        for (int nt = 0; nt < 4; nt++) {
            const int n = n0 + warp_n + nt * 8 + (lane & 3) * 2;
            const float b0 = bias[n], b1 = bias[n + 1];
            float2 v0 = make_float2(
                acch[mt][nt][0] + accl[mt][nt][0] * LO_SCALE + b0,
                acch[mt][nt][1] + accl[mt][nt][1] * LO_SCALE + b1);
            float2 v1 = make_float2(
                acch[mt][nt][2] + accl[mt][nt][2] * LO_SCALE + b0,
                acch[mt][nt][3] + accl[mt][nt][3] * LO_SCALE + b1);
            *(float2*)(C + (size_t)m * NH + n)       = v0;
            *(float2*)(C + (size_t)(m + 8) * NH + n) = v1;
        }
    }
}

// ============================================================================
// t = 0: h0 = tanh(xw[0]); write fp32 out[0] and fp16 state buf 0
// ============================================================================
__global__ __launch_bounds__(256) void tanh0_kernel(float* __restrict__ x)
{
    const size_t i = (size_t)blockIdx.x * blockDim.x + threadIdx.x;  // float4 idx
    float4 v = ((const float4*)x)[i];
    v.x = tanhf(v.x); v.y = tanhf(v.y); v.z = tanhf(v.z); v.w = tanhf(v.w);
    ((float4*)x)[i] = v;
    ((__half2*)g_H16[0])[i * 2 + 0] = __floats2half2_rn(v.x, v.y);
    ((__half2*)g_H16[0])[i * 2 + 1] = __floats2half2_rn(v.z, v.w);
}

// ============================================================================
// Persistent RNN recurrence: t = 1..511, per-m-group barriers (R9 — unchanged).
// 128 CTAs = 4 m-groups (64 rows) x 32 n-blocks (32 cols), 256 threads.
// W_hh fp16 hi+lo(x2048) slice RESIDENT in smem (160 KB).
// H (single fp16) streamed: K64 chunks, 3 stages x 10 KB, 16 iters/step.
// Split-K across warps: warps 0-3 even k16-slices, 4-7 odd.
// ============================================================================
#define PW_HI    0
#define PW_LO    81920
#define PH_BASE  163840
#define PH_STAGE 10240
#define PH_SUB   5120
#define PK_SMEM  194560

__global__ __launch_bounds__(256, 1) void rnn_persist_kernel(float* __restrict__ out)
{
    extern __shared__ char smem[];
    const uint32_t sb = smem_u32(smem);
    const int tid  = threadIdx.x;
    const int wid  = tid >> 5;
    const int lane = tid & 31;
    const int mb = blockIdx.x >> 5;    // 0..3  (m-group)
    const int nb = blockIdx.x & 31;    // 0..31
    const int m0 = mb * 64;
    const int n0 = nb * 32;
    const int warp_m = (wid & 3) * 16;   // 0..48
    const int kh     = wid >> 2;         // 0 = even k16 slices, 1 = odd

    // ---- Load resident W_hh fp16 slice (hi + scaled lo), pitch 80B ----
    for (int idx = tid; idx < 4096; idx += 256) {
        const int ch  = idx >> 7;          // 0..31  k32-chunk
        const int r   = (idx >> 2) & 31;   // 0..31  n-row
        const int seg = idx & 3;           // 0..3   16B seg
        const size_t g = (size_t)(n0 + r) * NH + ch * 32 + seg * 8;
        const uint32_t so = sb + ch * 2560 + r * 80 + seg * 16;
        CP16(so + PW_HI, g_Whh16_hi + g);
        CP16(so + PW_LO, g_Whh16_lo + g);
    }
    CP_COMMIT(); CP_WAIT(0); __syncthreads();

    const int hrow = tid >> 2;   // 0..63
    const int hseg = tid & 3;

    for (int t = 1; t < T_STEPS; t++) {
        const __half* Hh = g_H16[(t - 1) & 1];
        __half* HO = g_H16[t & 1];
        float* X = out + (size_t)t * BATCH * NH;

        // issue K64 chunk c into stage c%3 (hi only: 2 x CP16 per thread)
        auto issueH = [&](int c) {
            const uint32_t st = sb + PH_BASE + (c % 3) * PH_STAGE +
                                hrow * 80 + hseg * 16;
#pragma unroll
            for (int j = 0; j < 2; j++) {
                const size_t ga = (size_t)(m0 + hrow) * NH + c * 64 + j * 32 + hseg * 8;
                CP16(st + j * PH_SUB, Hh + ga);
            }
        };
        issueH(0); CP_COMMIT();
        issueH(1); CP_COMMIT();

        // Prefetch xw tile (used by kh=0 warps in the epilogue)
        float2 xwr[2][4];
        if (kh == 0) {
            const int mrow = m0 + warp_m + (lane >> 2);
#pragma unroll
            for (int half = 0; half < 2; half++)
#pragma unroll
                for (int nt = 0; nt < 4; nt++) {
                    const int m = mrow + half * 8;
                    const int n = n0 + nt * 8 + (lane & 3) * 2;
                    xwr[half][nt] = *(const float2*)(X + (size_t)m * NH + n);
                }
        }

        float acch[4][4], accl[4][4];
#pragma unroll
        for (int i = 0; i < 4; i++)
#pragma unroll
            for (int j = 0; j < 4; j++) { acch[i][j] = 0.f; accl[i][j] = 0.f; }

        for (int it = 0; it < 16; it++) {
            CP_WAIT(1);
            __syncthreads();
            if (it + 2 < 16) issueH(it + 2);
            CP_COMMIT();

            const uint32_t hst = sb + PH_BASE + (it % 3) * PH_STAGE;
#pragma unroll
            for (int j = 0; j < 2; j++) {
                const int slice = 2 * j + kh;        // this warp's k16 slice (0..3)
                const int sub = slice >> 1;
                const uint32_t kb = (slice & 1) * 32;
                uint32_t ah[4];
                {
                    const uint32_t ad = hst + sub * PH_SUB +
                                        (warp_m + (lane & 15)) * 80 +
                                        ((lane >> 4) * 16) + kb;
                    ldsm4(ah, ad);
                }
                uint32_t bh[4][2], bl[4][2];
#pragma unroll
                for (int g = 0; g < 2; g++) {
                    const int nr = g * 16 + (lane & 7) + ((lane >> 4) << 3);
                    const uint32_t bd = sb + (it * 2 + sub) * 2560 + nr * 80 +
                                        (((lane >> 3) & 1) * 16) + kb;
                    uint32_t tmp[4];
                    ldsm4(tmp, bd + PW_HI);
                    bh[g * 2][0] = tmp[0]; bh[g * 2][1] = tmp[1];
                    bh[g * 2 + 1][0] = tmp[2]; bh[g * 2 + 1][1] = tmp[3];
                    ldsm4(tmp, bd + PW_LO);
                    bl[g * 2][0] = tmp[0]; bl[g * 2][1] = tmp[1];
                    bl[g * 2 + 1][0] = tmp[2]; bl[g * 2 + 1][1] = tmp[3];
                }
#pragma unroll
                for (int nt = 0; nt < 4; nt++) mma_f16(acch[nt], ah, bh[nt]);
#pragma unroll
                for (int nt = 0; nt < 4; nt++) mma_f16(accl[nt], ah, bl[nt]);
            }
        }

        // ---- Cross-warp split-K reduction via smem (reuse drained H stage) ----
        CP_WAIT(0);
        __syncthreads();
        float* rbuf = (float*)(smem + PH_BASE);   // 64 x 32 fp32 = 8 KB
        if (kh == 1) {
            const int mrow = warp_m + (lane >> 2);
#pragma unroll
            for (int half = 0; half < 2; half++)
#pragma unroll
                for (int nt = 0; nt < 4; nt++) {
                    const int m = mrow + half * 8;
                    const int n = nt * 8 + (lane & 3) * 2;
                    *(float2*)(rbuf + m * 32 + n) = make_float2(
                        acch[nt][half * 2 + 0] + accl[nt][half * 2 + 0] * LO_SCALE,
                        acch[nt][half * 2 + 1] + accl[nt][half * 2 + 1] * LO_SCALE);
                }
        }
        __syncthreads();

        // ---- Epilogue (warps 0-3): h = tanh(xw + self + other) ----
        if (kh == 0) {
            const int mrow = m0 + warp_m + (lane >> 2);
#pragma unroll
            for (int half = 0; half < 2; half++) {
                const int m = mrow + half * 8;
                const int mloc = warp_m + (lane >> 2) + half * 8;
#pragma unroll
                for (int nt = 0; nt < 4; nt++) {
                    const int nloc = nt * 8 + (lane & 3) * 2;
                    const int n = n0 + nloc;
                    const size_t off = (size_t)m * NH + n;
                    const float2 other = *(const float2*)(rbuf + mloc * 32 + nloc);
                    const float s0 = acch[nt][half * 2 + 0] +
                                     accl[nt][half * 2 + 0] * LO_SCALE + other.x;
                    const float s1 = acch[nt][half * 2 + 1] +
                                     accl[nt][half * 2 + 1] * LO_SCALE + other.y;
                    const float v0 = tanhf(xwr[half][nt].x + s0);
                    const float v1 = tanhf(xwr[half][nt].y + s1);
                    *(float2*)(X + off) = make_float2(v0, v1);
                    *(__half2*)(HO + off) = __floats2half2_rn(v0, v1);
                    if (t == T_STEPS - 1)
                        *(float2*)(out + (size_t)T_STEPS * BATCH * NH + off) =
                            make_float2(v0, v1);
                }
            }
        }

        // ---- Per-m-group barrier between steps (32 CTAs) ----
        __syncthreads();
        if (tid == 0) grid_bar(mb);
        __syncthreads();
    }
}

// ============================================================================
// Launch
// ============================================================================
extern "C" void kernel_launch(void* const* d_in, const int* in_sizes, int n_in,
                              void* d_out, int out_size)
{
    const float* inputs = (const float*)d_in[0];   // [T, B, NIN]
    const float* W_xh   = (const float*)d_in[1];   // [NIN, NH]
    const float* W_hh   = (const float*)d_in[2];   // [NH, NH]
    const float* b_h    = (const float*)d_in[3];   // [NH]
    float* out = (float*)d_out;                    // [T, B, NH] + [B, NH]

    const size_t step_elems = (size_t)BATCH * NH;  // 262144

    static bool attr_set = false;
    if (!attr_set) {
        cudaFuncSetAttribute(gemm1_kernel,
                             cudaFuncAttributeMaxDynamicSharedMemorySize, G1_SMEM);
        cudaFuncSetAttribute(rnn_persist_kernel,
                             cudaFuncAttributeMaxDynamicSharedMemorySize, PK_SMEM);
        attr_set = true;
    }

    // Prep: split weights (transposed, fp16 hi/lo) and convert inputs to fp16
    {
        dim3 grid(NH / 32, NIN / 32);
        split_w16_kernel<<<grid, 256>>>(W_xh, 0);
        split_w16_kernel<<<grid, 256>>>(W_hh, 1);
        conv_a_kernel<<<8192, 256>>>(inputs);
    }

    // Phase 1: xw = inputs @ W_xh + b_h  -> out[0..T)
    {
        dim3 grid(NH / 128, M_TOTAL / 128);   // (8, 1024)
        gemm1_kernel<<<grid, 512, G1_SMEM>>>(b_h, out);
    }

    // t = 0
    tanh0_kernel<<<(int)(step_elems / 4 / 256), 256>>>(out);

    // t = 1..T-1 in ONE persistent kernel (also writes final_state tail)
    rnn_persist_kernel<<<PK_CTAS, 256, PK_SMEM>>>(out);
}

// round 11
// speedup vs baseline: 2.6693x; 1.2244x over previous
#include <cuda_runtime.h>
#include <cuda_fp16.h>
#include <math.h>
#include <stdint.h>

// Problem shapes (fixed by reference)
#define T_STEPS 512
#define BATCH   256
#define NIN     1024
#define NH      1024
#define M_TOTAL (T_STEPS * BATCH)   // 131072

// ============================================================================
// Device scratch (static — no allocation allowed)
// ============================================================================
__device__ __half g_A16[(size_t)M_TOTAL * NIN];          // inputs fp16, [M][K]
__device__ __half g_Wxh16[(size_t)NH * NIN];             // W_xh^T fp16, [N][K]
__device__ __half g_Whh16[(size_t)NH * NH];              // W_hh^T fp16, [N][K]
__device__ __half g_H16[2][(size_t)BATCH * NH];          // state fp16, double buffered

// Per-m-group barrier state (4 groups of 32 CTAs); zero-init, phase monotonic
__device__ unsigned g_bar_count[4];
__device__ unsigned g_bar_phase[4];

// ============================================================================
// PTX helpers (all sm_80-era: compile for plain compute_103)
// ============================================================================
__device__ __forceinline__ uint32_t smem_u32(const void* p) {
    uint32_t a;
    asm("{ .reg .u64 t; cvta.to.shared.u64 t, %1; cvt.u32.u64 %0, t; }"
        : "=r"(a) : "l"(p));
    return a;
}

#define CP16(dst, src) \
    asm volatile("cp.async.cg.shared.global [%0], [%1], 16;" :: "r"(dst), "l"(src))
#define CP_COMMIT() asm volatile("cp.async.commit_group;" ::: "memory")
#define CP_WAIT(n)  asm volatile("cp.async.wait_group %0;" :: "n"(n) : "memory")

__device__ __forceinline__ void ldsm4(uint32_t r[4], uint32_t addr) {
    asm volatile("ldmatrix.sync.aligned.m8n8.x4.shared.b16 {%0,%1,%2,%3}, [%4];"
                 : "=r"(r[0]), "=r"(r[1]), "=r"(r[2]), "=r"(r[3]) : "r"(addr));
}

__device__ __forceinline__ void mma_f16(float c[4], const uint32_t a[4],
                                        const uint32_t b[2]) {
    asm volatile(
        "mma.sync.aligned.m16n8k16.row.col.f32.f16.f16.f32 "
        "{%0,%1,%2,%3}, {%4,%5,%6,%7}, {%8,%9}, {%0,%1,%2,%3};"
        : "+f"(c[0]), "+f"(c[1]), "+f"(c[2]), "+f"(c[3])
        : "r"(a[0]), "r"(a[1]), "r"(a[2]), "r"(a[3]), "r"(b[0]), "r"(b[1]));
}

__device__ __forceinline__ unsigned ld_acq(const unsigned* p) {
    unsigned v;
    asm volatile("ld.acquire.gpu.global.u32 %0, [%1];" : "=r"(v) : "l"(p) : "memory");
    return v;
}
__device__ __forceinline__ void st_rel(unsigned* p, unsigned v) {
    asm volatile("st.release.gpu.global.u32 [%0], %1;" :: "l"(p), "r"(v) : "memory");
}

#define PK_CTAS  128
#define PK_GROUP 32   // CTAs per m-group barrier

__device__ __forceinline__ void grid_bar(int g) {
    unsigned ph = ld_acq(&g_bar_phase[g]);
    __threadfence();
    unsigned old = atomicAdd(&g_bar_count[g], 1);
    if (old == PK_GROUP - 1) {
        g_bar_count[g] = 0;
        st_rel(&g_bar_phase[g], ph + 1);
    } else {
        while (ld_acq(&g_bar_phase[g]) == ph) { }
    }
}

// ============================================================================
// Prep: transpose a weight [K][N] fp32 -> [N][K] fp16
// which = 0 -> g_Wxh16, 1 -> g_Whh16
// ============================================================================
__global__ __launch_bounds__(256) void conv_w16_kernel(const float* __restrict__ W,
                                                       int which)
{
    __shared__ float tile[32][33];
    __half* out16 = which ? g_Whh16 : g_Wxh16;
    const int bx = blockIdx.x * 32;   // n block
    const int by = blockIdx.y * 32;   // k block
    const int tx = threadIdx.x & 31;
    const int ty = threadIdx.x >> 5;
    for (int i = ty; i < 32; i += 8)
        tile[i][tx] = W[(size_t)(by + i) * NH + bx + tx];
    __syncthreads();
    for (int i = ty; i < 32; i += 8) {
        float x = tile[tx][i];                 // W[by+tx][bx+i]
        out16[(size_t)(bx + i) * NIN + by + tx] = __float2half(x);
    }
}

// ============================================================================
// Prep: inputs fp32 [M][K] -> g_A16 fp16 (same layout)
// ============================================================================
__global__ __launch_bounds__(256) void conv_a_kernel(const float* __restrict__ A)
{
    const size_t n4 = (size_t)M_TOTAL * NIN / 4;
    size_t i = (size_t)blockIdx.x * blockDim.x + threadIdx.x;
    const size_t stride = (size_t)gridDim.x * blockDim.x;
    for (; i < n4; i += stride) {
        float4 v = ((const float4*)A)[i];
        ((__half2*)g_A16)[i * 2 + 0] = __floats2half2_rn(v.x, v.y);
        ((__half2*)g_A16)[i * 2 + 1] = __floats2half2_rn(v.z, v.w);
    }
}

// ============================================================================
// Phase 1 GEMM: C[M,N] = A16 @ W16^T + bias  (single-term fp16 HMMA)
// CTA 128x128, 256 thr (8 warps 2x4, warp tile 64x32), K-chunk 32, 3 stages.
// smem stage: A16[128][80B] | W16[128][80B].  2 CTAs/SM.
// ============================================================================
#define G1_ARR_B   (128 * 80)                // 10240 B per array
#define G1_STAGE_B (2 * G1_ARR_B)            // 20480 B per stage
#define G1_SMEM    (3 * G1_STAGE_B)          // 61440 B

__global__ __launch_bounds__(256, 2) void gemm1_kernel(
    const float* __restrict__ bias, float* __restrict__ C)
{
    extern __shared__ char smem[];
    const uint32_t sb0 = smem_u32(smem);
    const int tid  = threadIdx.x;
    const int wid  = tid >> 5;
    const int lane = tid & 31;
    const int m0 = blockIdx.y * 128;
    const int n0 = blockIdx.x * 128;
    const int warp_m = (wid >> 2) * 64;
    const int warp_n = (wid & 3) * 32;

    float acc[4][4][4];
#pragma unroll
    for (int i = 0; i < 4; i++)
#pragma unroll
        for (int j = 0; j < 4; j++)
#pragma unroll
            for (int k = 0; k < 4; k++) acc[i][j][k] = 0.f;

    const int crow = tid >> 2;       // 0..63
    const int cseg = tid & 3;        // 0..3 (16B units)

    auto issue = [&](int c, int s) {
        const uint32_t st = sb0 + s * G1_STAGE_B;
        const int kb = c * 32 + cseg * 8;
#pragma unroll
        for (int h = 0; h < 2; h++) {
            const int r = crow + h * 64;
            const uint32_t so = r * 80 + cseg * 16;
            CP16(st + so,            g_A16 + (size_t)(m0 + r) * NIN + kb);
            CP16(st + G1_ARR_B + so, g_Wxh16 + (size_t)(n0 + r) * NIN + kb);
        }
    };

    issue(0, 0); CP_COMMIT();
    issue(1, 1); CP_COMMIT();

    for (int it = 0; it < 32; it++) {
        CP_WAIT(1);
        __syncthreads();
        if (it + 2 < 32) issue(it + 2, (it + 2) % 3);
        CP_COMMIT();

        const uint32_t st = sb0 + (it % 3) * G1_STAGE_B;
#pragma unroll
        for (int ks = 0; ks < 2; ks++) {
            const uint32_t kb = ks * 32;
            uint32_t ah[4][4];
#pragma unroll
            for (int mt = 0; mt < 4; mt++) {
                const int mr = warp_m + mt * 16 + (lane & 15);
                ldsm4(ah[mt], st + mr * 80 + ((lane >> 4) * 16) + kb);
            }
            uint32_t bh[4][2];
#pragma unroll
            for (int g = 0; g < 2; g++) {
                const int nr = warp_n + g * 16 + (lane & 7) + ((lane >> 4) << 3);
                uint32_t t[4];
                ldsm4(t, st + G1_ARR_B + nr * 80 + (((lane >> 3) & 1) * 16) + kb);
                bh[g * 2][0] = t[0]; bh[g * 2][1] = t[1];
                bh[g * 2 + 1][0] = t[2]; bh[g * 2 + 1][1] = t[3];
            }
#pragma unroll
            for (int mt = 0; mt < 4; mt++)
#pragma unroll
                for (int nt = 0; nt < 4; nt++)
                    mma_f16(acc[mt][nt], ah[mt], bh[nt]);
        }
    }

#pragma unroll
    for (int mt = 0; mt < 4; mt++) {
        const int m = m0 + warp_m + mt * 16 + (lane >> 2);
#pragma unroll
        for (int nt = 0; nt < 4; nt++) {
            const int n = n0 + warp_n + nt * 8 + (lane & 3) * 2;
            const float b0 = bias[n], b1 = bias[n + 1];
            float2 v0 = make_float2(acc[mt][nt][0] + b0, acc[mt][nt][1] + b1);
            float2 v1 = make_float2(acc[mt][nt][2] + b0, acc[mt][nt][3] + b1);
            *(float2*)(C + (size_t)m * NH + n)       = v0;
            *(float2*)(C + (size_t)(m + 8) * NH + n) = v1;
        }
    }
}

// ============================================================================
// t = 0: h0 = tanh(xw[0]); write fp32 out[0] and fp16 state buf 0
// ============================================================================
__global__ __launch_bounds__(256) void tanh0_kernel(float* __restrict__ x)
{
    const size_t i = (size_t)blockIdx.x * blockDim.x + threadIdx.x;  // float4 idx
    float4 v = ((const float4*)x)[i];
    v.x = tanhf(v.x); v.y = tanhf(v.y); v.z = tanhf(v.z); v.w = tanhf(v.w);
    ((float4*)x)[i] = v;
    ((__half2*)g_H16[0])[i * 2 + 0] = __floats2half2_rn(v.x, v.y);
    ((__half2*)g_H16[0])[i * 2 + 1] = __floats2half2_rn(v.z, v.w);
}

// ============================================================================
// Persistent RNN recurrence: t = 1..511, per-m-group barriers.
// 128 CTAs = 4 m-groups (64 rows) x 32 n-blocks (32 cols), 256 threads.
// W_hh fp16 slice (32 n-rows x 1024 K) RESIDENT in smem (80 KB).
// H (fp16) streamed: K64 chunks, 3 stages x 10 KB, 16 iters/step.
// Split-K across warps: warps 0-3 even k16-slices, 4-7 odd. Single fp16 term.
// ============================================================================
#define PW_HI    0
#define PH_BASE  81920
#define PH_STAGE 10240
#define PH_SUB   5120
#define PK_SMEM  112640

__global__ __launch_bounds__(256, 1) void rnn_persist_kernel(float* __restrict__ out)
{
    extern __shared__ char smem[];
    const uint32_t sb = smem_u32(smem);
    const int tid  = threadIdx.x;
    const int wid  = tid >> 5;
    const int lane = tid & 31;
    const int mb = blockIdx.x >> 5;    // 0..3  (m-group)
    const int nb = blockIdx.x & 31;    // 0..31
    const int m0 = mb * 64;
    const int n0 = nb * 32;
    const int warp_m = (wid & 3) * 16;   // 0..48
    const int kh     = wid >> 2;         // 0 = even k16 slices, 1 = odd

    // ---- Load resident W_hh fp16 slice, chunked K-major, pitch 80B ----
    for (int idx = tid; idx < 4096; idx += 256) {
        const int ch  = idx >> 7;          // 0..31  k32-chunk
        const int r   = (idx >> 2) & 31;   // 0..31  n-row
        const int seg = idx & 3;           // 0..3   16B seg
        CP16(sb + PW_HI + ch * 2560 + r * 80 + seg * 16,
             g_Whh16 + (size_t)(n0 + r) * NH + ch * 32 + seg * 8);
    }
    CP_COMMIT(); CP_WAIT(0); __syncthreads();

    const int hrow = tid >> 2;   // 0..63
    const int hseg = tid & 3;

    for (int t = 1; t < T_STEPS; t++) {
        const __half* Hh = g_H16[(t - 1) & 1];
        __half* HO = g_H16[t & 1];
        float* X = out + (size_t)t * BATCH * NH;

        // issue K64 chunk c into stage c%3 (2 x CP16 per thread)
        auto issueH = [&](int c) {
            const uint32_t st = sb + PH_BASE + (c % 3) * PH_STAGE +
                                hrow * 80 + hseg * 16;
#pragma unroll
            for (int j = 0; j < 2; j++) {
                CP16(st + j * PH_SUB,
                     Hh + (size_t)(m0 + hrow) * NH + c * 64 + j * 32 + hseg * 8);
            }
        };
        issueH(0); CP_COMMIT();
        issueH(1); CP_COMMIT();

        // Prefetch xw tile (used by kh=0 warps in the epilogue)
        float2 xwr[2][4];
        if (kh == 0) {
            const int mrow = m0 + warp_m + (lane >> 2);
#pragma unroll
            for (int half = 0; half < 2; half++)
#pragma unroll
                for (int nt = 0; nt < 4; nt++) {
                    const int m = mrow + half * 8;
                    const int n = n0 + nt * 8 + (lane & 3) * 2;
                    xwr[half][nt] = *(const float2*)(X + (size_t)m * NH + n);
                }
        }

        float acc[4][4];
#pragma unroll
        for (int i = 0; i < 4; i++)
#pragma unroll
            for (int j = 0; j < 4; j++) acc[i][j] = 0.f;

        for (int it = 0; it < 16; it++) {
            CP_WAIT(1);
            __syncthreads();
            if (it + 2 < 16) issueH(it + 2);
            CP_COMMIT();

            const uint32_t hst = sb + PH_BASE + (it % 3) * PH_STAGE;
#pragma unroll
            for (int j = 0; j < 2; j++) {
                const int slice = 2 * j + kh;        // this warp's k16 slice (0..3)
                const int sub = slice >> 1;
                const uint32_t kb = (slice & 1) * 32;
                uint32_t ah[4];
                ldsm4(ah, hst + sub * PH_SUB + (warp_m + (lane & 15)) * 80 +
                          ((lane >> 4) * 16) + kb);
                uint32_t bh[4][2];
#pragma unroll
                for (int g = 0; g < 2; g++) {
                    const int nr = g * 16 + (lane & 7) + ((lane >> 4) << 3);
                    uint32_t tmp[4];
                    ldsm4(tmp, sb + PW_HI + (it * 2 + sub) * 2560 + nr * 80 +
                               (((lane >> 3) & 1) * 16) + kb);
                    bh[g * 2][0] = tmp[0]; bh[g * 2][1] = tmp[1];
                    bh[g * 2 + 1][0] = tmp[2]; bh[g * 2 + 1][1] = tmp[3];
                }
#pragma unroll
                for (int nt = 0; nt < 4; nt++) mma_f16(acc[nt], ah, bh[nt]);
            }
        }

        // ---- Cross-warp split-K reduction via smem (reuse drained H stage) ----
        CP_WAIT(0);
        __syncthreads();
        float* rbuf = (float*)(smem + PH_BASE);   // 64 x 32 fp32 = 8 KB
        if (kh == 1) {
            const int mrow = warp_m + (lane >> 2);
#pragma unroll
            for (int half = 0; half < 2; half++)
#pragma unroll
                for (int nt = 0; nt < 4; nt++) {
                    const int m = mrow + half * 8;
                    const int n = nt * 8 + (lane & 3) * 2;
                    *(float2*)(rbuf + m * 32 + n) = make_float2(
                        acc[nt][half * 2 + 0], acc[nt][half * 2 + 1]);
                }
        }
        __syncthreads();

        // ---- Epilogue (warps 0-3): h = tanh(xw + self + other) ----
        if (kh == 0) {
            const int mrow = m0 + warp_m + (lane >> 2);
#pragma unroll
            for (int half = 0; half < 2; half++) {
                const int m = mrow + half * 8;
                const int mloc = warp_m + (lane >> 2) + half * 8;
#pragma unroll
                for (int nt = 0; nt < 4; nt++) {
                    const int nloc = nt * 8 + (lane & 3) * 2;
                    const int n = n0 + nloc;
                    const size_t off = (size_t)m * NH + n;
                    const float2 other = *(const float2*)(rbuf + mloc * 32 + nloc);
                    const float s0 = acc[nt][half * 2 + 0] + other.x;
                    const float s1 = acc[nt][half * 2 + 1] + other.y;
                    const float v0 = tanhf(xwr[half][nt].x + s0);
                    const float v1 = tanhf(xwr[half][nt].y + s1);
                    *(float2*)(X + off) = make_float2(v0, v1);
                    *(__half2*)(HO + off) = __floats2half2_rn(v0, v1);
                    if (t == T_STEPS - 1)
                        *(float2*)(out + (size_t)T_STEPS * BATCH * NH + off) =
                            make_float2(v0, v1);
                }
            }
        }

        // ---- Per-m-group barrier between steps (32 CTAs) ----
        __syncthreads();
        if (tid == 0) grid_bar(mb);
        __syncthreads();
    }
}

// ============================================================================
// Launch
// ============================================================================
extern "C" void kernel_launch(void* const* d_in, const int* in_sizes, int n_in,
                              void* d_out, int out_size)
{
    const float* inputs = (const float*)d_in[0];   // [T, B, NIN]
    const float* W_xh   = (const float*)d_in[1];   // [NIN, NH]
    const float* W_hh   = (const float*)d_in[2];   // [NH, NH]
    const float* b_h    = (const float*)d_in[3];   // [NH]
    float* out = (float*)d_out;                    // [T, B, NH] + [B, NH]

    const size_t step_elems = (size_t)BATCH * NH;  // 262144

    static bool attr_set = false;
    if (!attr_set) {
        cudaFuncSetAttribute(gemm1_kernel,
                             cudaFuncAttributeMaxDynamicSharedMemorySize, G1_SMEM);
        cudaFuncSetAttribute(rnn_persist_kernel,
                             cudaFuncAttributeMaxDynamicSharedMemorySize, PK_SMEM);
        attr_set = true;
    }

    // Prep: transpose weights to fp16 [N][K]; convert inputs to fp16
    {
        dim3 grid(NH / 32, NIN / 32);
        conv_w16_kernel<<<grid, 256>>>(W_xh, 0);
        conv_w16_kernel<<<grid, 256>>>(W_hh, 1);
        conv_a_kernel<<<8192, 256>>>(inputs);
    }

    // Phase 1: xw = inputs @ W_xh + b_h  -> out[0..T)
    {
        dim3 grid(NH / 128, M_TOTAL / 128);   // (8, 1024)
        gemm1_kernel<<<grid, 256, G1_SMEM>>>(b_h, out);
    }

    // t = 0
    tanh0_kernel<<<(int)(step_elems / 4 / 256), 256>>>(out);

    // t = 1..T-1 in ONE persistent kernel (also writes final_state tail)
    rnn_persist_kernel<<<PK_CTAS, 256, PK_SMEM>>>(out);
}

// round 12
// speedup vs baseline: 3.3503x; 1.2551x over previous
#include <cuda_runtime.h>
#include <cuda_fp16.h>
#include <math.h>
#include <stdint.h>

// Problem shapes (fixed by reference)
#define T_STEPS 512
#define BATCH   256
#define NIN     1024
#define NH      1024
#define M_TOTAL (T_STEPS * BATCH)   // 131072

// ============================================================================
// Device scratch (static — no allocation allowed)
// ============================================================================
__device__ __half g_A16[(size_t)M_TOTAL * NIN];          // inputs fp16, [M][K]
__device__ __half g_Wxh16[(size_t)NH * NIN];             // W_xh^T fp16, [N][K]
__device__ __half g_Whh16[(size_t)NH * NH];              // W_hh^T fp16, [N][K]
__device__ __half g_H16[2][(size_t)BATCH * NH];          // state fp16, double buffered

// Per-m-group barrier state (8 groups of 16 CTAs); zero-init, phase monotonic
__device__ unsigned g_bar_count[8];
__device__ unsigned g_bar_phase[8];

// ============================================================================
// PTX helpers (all sm_80-era: compile for plain compute_103)
// ============================================================================
__device__ __forceinline__ uint32_t smem_u32(const void* p) {
    uint32_t a;
    asm("{ .reg .u64 t; cvta.to.shared.u64 t, %1; cvt.u32.u64 %0, t; }"
        : "=r"(a) : "l"(p));
    return a;
}

#define CP16(dst, src) \
    asm volatile("cp.async.cg.shared.global [%0], [%1], 16;" :: "r"(dst), "l"(src))
#define CP_COMMIT() asm volatile("cp.async.commit_group;" ::: "memory")
#define CP_WAIT(n)  asm volatile("cp.async.wait_group %0;" :: "n"(n) : "memory")

__device__ __forceinline__ void ldsm4(uint32_t r[4], uint32_t addr) {
    asm volatile("ldmatrix.sync.aligned.m8n8.x4.shared.b16 {%0,%1,%2,%3}, [%4];"
                 : "=r"(r[0]), "=r"(r[1]), "=r"(r[2]), "=r"(r[3]) : "r"(addr));
}

__device__ __forceinline__ void mma_f16(float c[4], const uint32_t a[4],
                                        const uint32_t b[2]) {
    asm volatile(
        "mma.sync.aligned.m16n8k16.row.col.f32.f16.f16.f32 "
        "{%0,%1,%2,%3}, {%4,%5,%6,%7}, {%8,%9}, {%0,%1,%2,%3};"
        : "+f"(c[0]), "+f"(c[1]), "+f"(c[2]), "+f"(c[3])
        : "r"(a[0]), "r"(a[1]), "r"(a[2]), "r"(a[3]), "r"(b[0]), "r"(b[1]));
}

__device__ __forceinline__ unsigned ld_acq(const unsigned* p) {
    unsigned v;
    asm volatile("ld.acquire.gpu.global.u32 %0, [%1];" : "=r"(v) : "l"(p) : "memory");
    return v;
}
__device__ __forceinline__ void st_rel(unsigned* p, unsigned v) {
    asm volatile("st.release.gpu.global.u32 [%0], %1;" :: "l"(p), "r"(v) : "memory");
}

#define PK_CTAS  128
#define PK_GROUP 16   // CTAs per m-group barrier

__device__ __forceinline__ void grid_bar(int g) {
    unsigned ph = ld_acq(&g_bar_phase[g]);
    __threadfence();
    unsigned old = atomicAdd(&g_bar_count[g], 1);
    if (old == PK_GROUP - 1) {
        g_bar_count[g] = 0;
        st_rel(&g_bar_phase[g], ph + 1);
    } else {
        while (ld_acq(&g_bar_phase[g]) == ph) { }
    }
}

// ============================================================================
// Prep: transpose a weight [K][N] fp32 -> [N][K] fp16
// which = 0 -> g_Wxh16, 1 -> g_Whh16
// ============================================================================
__global__ __launch_bounds__(256) void conv_w16_kernel(const float* __restrict__ W,
                                                       int which)
{
    __shared__ float tile[32][33];
    __half* out16 = which ? g_Whh16 : g_Wxh16;
    const int bx = blockIdx.x * 32;   // n block
    const int by = blockIdx.y * 32;   // k block
    const int tx = threadIdx.x & 31;
    const int ty = threadIdx.x >> 5;
    for (int i = ty; i < 32; i += 8)
        tile[i][tx] = W[(size_t)(by + i) * NH + bx + tx];
    __syncthreads();
    for (int i = ty; i < 32; i += 8) {
        float x = tile[tx][i];                 // W[by+tx][bx+i]
        out16[(size_t)(bx + i) * NIN + by + tx] = __float2half(x);
    }
}

// ============================================================================
// Prep: inputs fp32 [M][K] -> g_A16 fp16 (same layout)
// ============================================================================
__global__ __launch_bounds__(256) void conv_a_kernel(const float* __restrict__ A)
{
    const size_t n4 = (size_t)M_TOTAL * NIN / 4;
    size_t i = (size_t)blockIdx.x * blockDim.x + threadIdx.x;
    const size_t stride = (size_t)gridDim.x * blockDim.x;
    for (; i < n4; i += stride) {
        float4 v = ((const float4*)A)[i];
        ((__half2*)g_A16)[i * 2 + 0] = __floats2half2_rn(v.x, v.y);
        ((__half2*)g_A16)[i * 2 + 1] = __floats2half2_rn(v.z, v.w);
    }
}

// ============================================================================
// Phase 1 GEMM: C[M,N] = A16 @ W16^T + bias  (single-term fp16 HMMA)
// CTA 128x128, 256 thr (8 warps 2x4, warp tile 64x32), K-chunk 32, 3 stages.
// (R11 configuration — unchanged.)
// ============================================================================
#define G1_ARR_B   (128 * 80)                // 10240 B per array
#define G1_STAGE_B (2 * G1_ARR_B)            // 20480 B per stage
#define G1_SMEM    (3 * G1_STAGE_B)          // 61440 B

__global__ __launch_bounds__(256, 2) void gemm1_kernel(
    const float* __restrict__ bias, float* __restrict__ C)
{
    extern __shared__ char smem[];
    const uint32_t sb0 = smem_u32(smem);
    const int tid  = threadIdx.x;
    const int wid  = tid >> 5;
    const int lane = tid & 31;
    const int m0 = blockIdx.y * 128;
    const int n0 = blockIdx.x * 128;
    const int warp_m = (wid >> 2) * 64;
    const int warp_n = (wid & 3) * 32;

    float acc[4][4][4];
#pragma unroll
    for (int i = 0; i < 4; i++)
#pragma unroll
        for (int j = 0; j < 4; j++)
#pragma unroll
            for (int k = 0; k < 4; k++) acc[i][j][k] = 0.f;

    const int crow = tid >> 2;       // 0..63
    const int cseg = tid & 3;        // 0..3 (16B units)

    auto issue = [&](int c, int s) {
        const uint32_t st = sb0 + s * G1_STAGE_B;
        const int kb = c * 32 + cseg * 8;
#pragma unroll
        for (int h = 0; h < 2; h++) {
            const int r = crow + h * 64;
            const uint32_t so = r * 80 + cseg * 16;
            CP16(st + so,            g_A16 + (size_t)(m0 + r) * NIN + kb);
            CP16(st + G1_ARR_B + so, g_Wxh16 + (size_t)(n0 + r) * NIN + kb);
        }
    };

    issue(0, 0); CP_COMMIT();
    issue(1, 1); CP_COMMIT();

    for (int it = 0; it < 32; it++) {
        CP_WAIT(1);
        __syncthreads();
        if (it + 2 < 32) issue(it + 2, (it + 2) % 3);
        CP_COMMIT();

        const uint32_t st = sb0 + (it % 3) * G1_STAGE_B;
#pragma unroll
        for (int ks = 0; ks < 2; ks++) {
            const uint32_t kb = ks * 32;
            uint32_t ah[4][4];
#pragma unroll
            for (int mt = 0; mt < 4; mt++) {
                const int mr = warp_m + mt * 16 + (lane & 15);
                ldsm4(ah[mt], st + mr * 80 + ((lane >> 4) * 16) + kb);
            }
            uint32_t bh[4][2];
#pragma unroll
            for (int g = 0; g < 2; g++) {
                const int nr = warp_n + g * 16 + (lane & 7) + ((lane >> 4) << 3);
                uint32_t t[4];
                ldsm4(t, st + G1_ARR_B + nr * 80 + (((lane >> 3) & 1) * 16) + kb);
                bh[g * 2][0] = t[0]; bh[g * 2][1] = t[1];
                bh[g * 2 + 1][0] = t[2]; bh[g * 2 + 1][1] = t[3];
            }
#pragma unroll
            for (int mt = 0; mt < 4; mt++)
#pragma unroll
                for (int nt = 0; nt < 4; nt++)
                    mma_f16(acc[mt][nt], ah[mt], bh[nt]);
        }
    }

#pragma unroll
    for (int mt = 0; mt < 4; mt++) {
        const int m = m0 + warp_m + mt * 16 + (lane >> 2);
#pragma unroll
        for (int nt = 0; nt < 4; nt++) {
            const int n = n0 + warp_n + nt * 8 + (lane & 3) * 2;
            const float b0 = bias[n], b1 = bias[n + 1];
            float2 v0 = make_float2(acc[mt][nt][0] + b0, acc[mt][nt][1] + b1);
            float2 v1 = make_float2(acc[mt][nt][2] + b0, acc[mt][nt][3] + b1);
            *(float2*)(C + (size_t)m * NH + n)       = v0;
            *(float2*)(C + (size_t)(m + 8) * NH + n) = v1;
        }
    }
}

// ============================================================================
// t = 0: h0 = tanh(xw[0]); write fp32 out[0] and fp16 state buf 0
// ============================================================================
__global__ __launch_bounds__(256) void tanh0_kernel(float* __restrict__ x)
{
    const size_t i = (size_t)blockIdx.x * blockDim.x + threadIdx.x;  // float4 idx
    float4 v = ((const float4*)x)[i];
    v.x = tanhf(v.x); v.y = tanhf(v.y); v.z = tanhf(v.z); v.w = tanhf(v.w);
    ((float4*)x)[i] = v;
    ((__half2*)g_H16[0])[i * 2 + 0] = __floats2half2_rn(v.x, v.y);
    ((__half2*)g_H16[0])[i * 2 + 1] = __floats2half2_rn(v.z, v.w);
}

// ============================================================================
// Persistent RNN recurrence: t = 1..511.
// 128 CTAs = 8 m-groups (32 rows) x 16 n-blocks (64 cols), 256 threads.
// W_hh fp16 slice (64 n-rows x 1024 K) RESIDENT in smem (160 KB padded).
// H (fp16) streamed: K128 chunks, 3 stages x 10 KB, 8 iters/step.
// Split-K across warps: kh = wid>>2 selects the k16 half of each k32 sub.
// Warp tile 16m x 32n. Per-m-group barrier over 16 CTAs.
// smem: W: chunk ch(k32) at ch*5120, row r(0..63)*80, seg*16  -> 163840 B
//       H: PH_BASE + stage*10240 + sub(k32)*2560 + row(0..31)*80 + seg*16
// ============================================================================
#define PW_CHUNK 5120
#define PH_BASE  163840
#define PH_STAGE 10240
#define PH_SUB   2560
#define PK_SMEM  194560

__global__ __launch_bounds__(256, 1) void rnn_persist_kernel(float* __restrict__ out)
{
    extern __shared__ char smem[];
    const uint32_t sb = smem_u32(smem);
    const int tid  = threadIdx.x;
    const int wid  = tid >> 5;
    const int lane = tid & 31;
    const int mb = blockIdx.x >> 4;    // 0..7  (m-group)
    const int nb = blockIdx.x & 15;    // 0..15
    const int m0 = mb * 32;
    const int n0 = nb * 64;
    const int warp_m = (wid & 1) * 16;        // 0 or 16
    const int warp_n = ((wid >> 1) & 1) * 32; // 0 or 32
    const int kh     = wid >> 2;              // k16 half within each k32 sub
    const uint32_t kb = kh * 32;              // byte offset of this warp's k16

    // ---- Load resident W_hh fp16 slice: 64 rows x 1024 K, chunked k32 ----
    for (int idx = tid; idx < 8192; idx += 256) {
        const int ch  = idx >> 8;          // 0..31  k32-chunk
        const int r   = (idx >> 2) & 63;   // 0..63  n-row
        const int seg = idx & 3;           // 0..3   16B seg
        CP16(sb + ch * PW_CHUNK + r * 80 + seg * 16,
             g_Whh16 + (size_t)(n0 + r) * NH + ch * 32 + seg * 8);
    }
    CP_COMMIT(); CP_WAIT(0); __syncthreads();

    const int hrow = tid >> 3;   // 0..31
    const int hs   = tid & 7;    // seg pair base

    for (int t = 1; t < T_STEPS; t++) {
        const __half* Hh = g_H16[(t - 1) & 1];
        __half* HO = g_H16[t & 1];
        float* X = out + (size_t)t * BATCH * NH;

        // issue K128 chunk c into stage c%3 (2 x CP16 per thread)
        auto issueH = [&](int c) {
            const uint32_t st = sb + PH_BASE + (c % 3) * PH_STAGE;
#pragma unroll
            for (int j = 0; j < 2; j++) {
                const int seg = hs + j * 8;          // 0..15 (16B segs in K128)
                CP16(st + (seg >> 2) * PH_SUB + hrow * 80 + (seg & 3) * 16,
                     Hh + (size_t)(m0 + hrow) * NH + c * 128 + seg * 8);
            }
        };
        issueH(0); CP_COMMIT();
        issueH(1); CP_COMMIT();

        // Prefetch xw tile (used by kh=0 warps in the epilogue)
        float2 xwr[2][4];
        if (kh == 0) {
            const int mrow = m0 + warp_m + (lane >> 2);
#pragma unroll
            for (int half = 0; half < 2; half++)
#pragma unroll
                for (int nt = 0; nt < 4; nt++) {
                    const int m = mrow + half * 8;
                    const int n = n0 + warp_n + nt * 8 + (lane & 3) * 2;
                    xwr[half][nt] = *(const float2*)(X + (size_t)m * NH + n);
                }
        }

        float acc[4][4];
#pragma unroll
        for (int i = 0; i < 4; i++)
#pragma unroll
            for (int j = 0; j < 4; j++) acc[i][j] = 0.f;

        for (int it = 0; it < 8; it++) {
            CP_WAIT(1);
            __syncthreads();
            if (it + 2 < 8) issueH(it + 2);
            CP_COMMIT();

            const uint32_t hst = sb + PH_BASE + (it % 3) * PH_STAGE;
#pragma unroll
            for (int sub = 0; sub < 4; sub++) {
                uint32_t ah[4];
                ldsm4(ah, hst + sub * PH_SUB + (warp_m + (lane & 15)) * 80 +
                          ((lane >> 4) * 16) + kb);
                uint32_t bh[4][2];
#pragma unroll
                for (int g = 0; g < 2; g++) {
                    const int nr = warp_n + g * 16 + (lane & 7) + ((lane >> 4) << 3);
                    uint32_t tmp[4];
                    ldsm4(tmp, sb + (it * 4 + sub) * PW_CHUNK + nr * 80 +
                               (((lane >> 3) & 1) * 16) + kb);
                    bh[g * 2][0] = tmp[0]; bh[g * 2][1] = tmp[1];
                    bh[g * 2 + 1][0] = tmp[2]; bh[g * 2 + 1][1] = tmp[3];
                }
#pragma unroll
                for (int nt = 0; nt < 4; nt++) mma_f16(acc[nt], ah, bh[nt]);
            }
        }

        // ---- Cross-warp split-K reduction via smem (reuse drained H stages) ----
        CP_WAIT(0);
        __syncthreads();
        float* rbuf = (float*)(smem + PH_BASE);   // 32 x 64 fp32 = 8 KB
        if (kh == 1) {
            const int mrow = warp_m + (lane >> 2);
#pragma unroll
            for (int half = 0; half < 2; half++)
#pragma unroll
                for (int nt = 0; nt < 4; nt++) {
                    const int m = mrow + half * 8;
                    const int n = warp_n + nt * 8 + (lane & 3) * 2;
                    *(float2*)(rbuf + m * 64 + n) = make_float2(
                        acc[nt][half * 2 + 0], acc[nt][half * 2 + 1]);
                }
        }
        __syncthreads();

        // ---- Epilogue (kh=0 warps): h = tanh(xw + self + other) ----
        if (kh == 0) {
            const int mrow = m0 + warp_m + (lane >> 2);
#pragma unroll
            for (int half = 0; half < 2; half++) {
                const int m = mrow + half * 8;
                const int mloc = warp_m + (lane >> 2) + half * 8;
#pragma unroll
                for (int nt = 0; nt < 4; nt++) {
                    const int nloc = warp_n + nt * 8 + (lane & 3) * 2;
                    const int n = n0 + nloc;
                    const size_t off = (size_t)m * NH + n;
                    const float2 other = *(const float2*)(rbuf + mloc * 64 + nloc);
                    const float s0 = acc[nt][half * 2 + 0] + other.x;
                    const float s1 = acc[nt][half * 2 + 1] + other.y;
                    const float v0 = tanhf(xwr[half][nt].x + s0);
                    const float v1 = tanhf(xwr[half][nt].y + s1);
                    *(float2*)(X + off) = make_float2(v0, v1);
                    *(__half2*)(HO + off) = __floats2half2_rn(v0, v1);
                    if (t == T_STEPS - 1)
                        *(float2*)(out + (size_t)T_STEPS * BATCH * NH + off) =
                            make_float2(v0, v1);
                }
            }
        }

        // ---- Per-m-group barrier between steps (16 CTAs) ----
        __syncthreads();
        if (tid == 0) grid_bar(mb);
        __syncthreads();
    }
}

// ============================================================================
// Launch
// ============================================================================
extern "C" void kernel_launch(void* const* d_in, const int* in_sizes, int n_in,
                              void* d_out, int out_size)
{
    const float* inputs = (const float*)d_in[0];   // [T, B, NIN]
    const float* W_xh   = (const float*)d_in[1];   // [NIN, NH]
    const float* W_hh   = (const float*)d_in[2];   // [NH, NH]
    const float* b_h    = (const float*)d_in[3];   // [NH]
    float* out = (float*)d_out;                    // [T, B, NH] + [B, NH]

    const size_t step_elems = (size_t)BATCH * NH;  // 262144

    static bool attr_set = false;
    if (!attr_set) {
        cudaFuncSetAttribute(gemm1_kernel,
                             cudaFuncAttributeMaxDynamicSharedMemorySize, G1_SMEM);
        cudaFuncSetAttribute(rnn_persist_kernel,
                             cudaFuncAttributeMaxDynamicSharedMemorySize, PK_SMEM);
        attr_set = true;
    }

    // Prep: transpose weights to fp16 [N][K]; convert inputs to fp16
    {
        dim3 grid(NH / 32, NIN / 32);
        conv_w16_kernel<<<grid, 256>>>(W_xh, 0);
        conv_w16_kernel<<<grid, 256>>>(W_hh, 1);
        conv_a_kernel<<<8192, 256>>>(inputs);
    }

    // Phase 1: xw = inputs @ W_xh + b_h  -> out[0..T)
    {
        dim3 grid(NH / 128, M_TOTAL / 128);   // (8, 1024)
        gemm1_kernel<<<grid, 256, G1_SMEM>>>(b_h, out);
    }

    // t = 0
    tanh0_kernel<<<(int)(step_elems / 4 / 256), 256>>>(out);

    // t = 1..T-1 in ONE persistent kernel (also writes final_state tail)
    rnn_persist_kernel<<<PK_CTAS, 256, PK_SMEM>>>(out);
}

// round 13
// speedup vs baseline: 3.5170x; 1.0497x over previous
#include <cuda_runtime.h>
#include <cuda_fp16.h>
#include <math.h>
#include <stdint.h>

// Problem shapes (fixed by reference)
#define T_STEPS 512
#define BATCH   256
#define NIN     1024
#define NH      1024
#define M_TOTAL (T_STEPS * BATCH)   // 131072

// ============================================================================
// Device scratch (static — no allocation allowed)
// ============================================================================
__device__ __half g_A16[(size_t)M_TOTAL * NIN];          // inputs fp16, [M][K]
__device__ __half g_Wxh16[(size_t)NH * NIN];             // W_xh^T fp16, [N][K]
__device__ __half g_Whh16[(size_t)NH * NH];              // W_hh^T fp16, [N][K]
__device__ __half g_H16[2][(size_t)BATCH * NH];          // state fp16, double buffered

// Per-m-group barrier state (8 groups of 16 CTAs); zero-init, phase monotonic
__device__ unsigned g_bar_count[8];
__device__ unsigned g_bar_phase[8];

// ============================================================================
// PTX helpers (all sm_80-era: compile for plain compute_103)
// ============================================================================
__device__ __forceinline__ uint32_t smem_u32(const void* p) {
    uint32_t a;
    asm("{ .reg .u64 t; cvta.to.shared.u64 t, %1; cvt.u32.u64 %0, t; }"
        : "=r"(a) : "l"(p));
    return a;
}

#define CP16(dst, src) \
    asm volatile("cp.async.cg.shared.global [%0], [%1], 16;" :: "r"(dst), "l"(src))
#define CP_COMMIT() asm volatile("cp.async.commit_group;" ::: "memory")
#define CP_WAIT(n)  asm volatile("cp.async.wait_group %0;" :: "n"(n) : "memory")

__device__ __forceinline__ void ldsm4(uint32_t r[4], uint32_t addr) {
    asm volatile("ldmatrix.sync.aligned.m8n8.x4.shared.b16 {%0,%1,%2,%3}, [%4];"
                 : "=r"(r[0]), "=r"(r[1]), "=r"(r[2]), "=r"(r[3]) : "r"(addr));
}

__device__ __forceinline__ void mma_f16(float c[4], const uint32_t a[4],
                                        const uint32_t b[2]) {
    asm volatile(
        "mma.sync.aligned.m16n8k16.row.col.f32.f16.f16.f32 "
        "{%0,%1,%2,%3}, {%4,%5,%6,%7}, {%8,%9}, {%0,%1,%2,%3};"
        : "+f"(c[0]), "+f"(c[1]), "+f"(c[2]), "+f"(c[3])
        : "r"(a[0]), "r"(a[1]), "r"(a[2]), "r"(a[3]), "r"(b[0]), "r"(b[1]));
}

__device__ __forceinline__ unsigned ld_acq(const unsigned* p) {
    unsigned v;
    asm volatile("ld.acquire.gpu.global.u32 %0, [%1];" : "=r"(v) : "l"(p) : "memory");
    return v;
}
__device__ __forceinline__ void st_rel(unsigned* p, unsigned v) {
    asm volatile("st.release.gpu.global.u32 [%0], %1;" :: "l"(p), "r"(v) : "memory");
}

#define PK_CTAS  128
#define PK_GROUP 16   // CTAs per m-group barrier

__device__ __forceinline__ void grid_bar(int g) {
    unsigned ph = ld_acq(&g_bar_phase[g]);
    __threadfence();
    unsigned old = atomicAdd(&g_bar_count[g], 1);
    if (old == PK_GROUP - 1) {
        g_bar_count[g] = 0;
        st_rel(&g_bar_phase[g], ph + 1);
    } else {
        while (ld_acq(&g_bar_phase[g]) == ph) { }
    }
}

// Dense 2048B-row layout with XOR swizzle inside each 128B block.
// gseg = 16B segment index within the row (0..127).
__device__ __forceinline__ uint32_t swz(int row, int gseg) {
    return (uint32_t)(row * 2048 + (gseg >> 3) * 128 + (((gseg ^ row) & 7) * 16));
}

// ============================================================================
// Prep: transpose a weight [K][N] fp32 -> [N][K] fp16
// which = 0 -> g_Wxh16, 1 -> g_Whh16
// ============================================================================
__global__ __launch_bounds__(256) void conv_w16_kernel(const float* __restrict__ W,
                                                       int which)
{
    __shared__ float tile[32][33];
    __half* out16 = which ? g_Whh16 : g_Wxh16;
    const int bx = blockIdx.x * 32;   // n block
    const int by = blockIdx.y * 32;   // k block
    const int tx = threadIdx.x & 31;
    const int ty = threadIdx.x >> 5;
    for (int i = ty; i < 32; i += 8)
        tile[i][tx] = W[(size_t)(by + i) * NH + bx + tx];
    __syncthreads();
    for (int i = ty; i < 32; i += 8) {
        float x = tile[tx][i];                 // W[by+tx][bx+i]
        out16[(size_t)(bx + i) * NIN + by + tx] = __float2half(x);
    }
}

// ============================================================================
// Prep: inputs fp32 [M][K] -> g_A16 fp16 (same layout)
// ============================================================================
__global__ __launch_bounds__(256) void conv_a_kernel(const float* __restrict__ A)
{
    const size_t n4 = (size_t)M_TOTAL * NIN / 4;
    size_t i = (size_t)blockIdx.x * blockDim.x + threadIdx.x;
    const size_t stride = (size_t)gridDim.x * blockDim.x;
    for (; i < n4; i += stride) {
        float4 v = ((const float4*)A)[i];
        ((__half2*)g_A16)[i * 2 + 0] = __floats2half2_rn(v.x, v.y);
        ((__half2*)g_A16)[i * 2 + 1] = __floats2half2_rn(v.z, v.w);
    }
}

// ============================================================================
// Phase 1 GEMM: C[M,N] = A16 @ W16^T + bias  (single-term fp16 HMMA)
// CTA 128x128, 256 thr (8 warps 2x4, warp tile 64x32), K-chunk 32, 4 stages.
// ============================================================================
#define G1_ARR_B   (128 * 80)                // 10240 B per array
#define G1_STAGE_B (2 * G1_ARR_B)            // 20480 B per stage
#define G1_SMEM    (4 * G1_STAGE_B)          // 81920 B

__global__ __launch_bounds__(256, 2) void gemm1_kernel(
    const float* __restrict__ bias, float* __restrict__ C)
{
    extern __shared__ char smem[];
    const uint32_t sb0 = smem_u32(smem);
    const int tid  = threadIdx.x;
    const int wid  = tid >> 5;
    const int lane = tid & 31;
    const int m0 = blockIdx.y * 128;
    const int n0 = blockIdx.x * 128;
    const int warp_m = (wid >> 2) * 64;
    const int warp_n = (wid & 3) * 32;

    float acc[4][4][4];
#pragma unroll
    for (int i = 0; i < 4; i++)
#pragma unroll
        for (int j = 0; j < 4; j++)
#pragma unroll
            for (int k = 0; k < 4; k++) acc[i][j][k] = 0.f;

    const int crow = tid >> 2;       // 0..63
    const int cseg = tid & 3;        // 0..3 (16B units)

    auto issue = [&](int c, int s) {
        const uint32_t st = sb0 + s * G1_STAGE_B;
        const int kb = c * 32 + cseg * 8;
#pragma unroll
        for (int h = 0; h < 2; h++) {
            const int r = crow + h * 64;
            const uint32_t so = r * 80 + cseg * 16;
            CP16(st + so,            g_A16 + (size_t)(m0 + r) * NIN + kb);
            CP16(st + G1_ARR_B + so, g_Wxh16 + (size_t)(n0 + r) * NIN + kb);
        }
    };

    issue(0, 0); CP_COMMIT();
    issue(1, 1); CP_COMMIT();
    issue(2, 2); CP_COMMIT();

    for (int it = 0; it < 32; it++) {
        CP_WAIT(2);
        __syncthreads();
        if (it + 3 < 32) issue(it + 3, (it + 3) & 3);
        CP_COMMIT();

        const uint32_t st = sb0 + (it & 3) * G1_STAGE_B;
#pragma unroll
        for (int ks = 0; ks < 2; ks++) {
            const uint32_t kb = ks * 32;
            uint32_t ah[4][4];
#pragma unroll
            for (int mt = 0; mt < 4; mt++) {
                const int mr = warp_m + mt * 16 + (lane & 15);
                ldsm4(ah[mt], st + mr * 80 + ((lane >> 4) * 16) + kb);
            }
            uint32_t bh[4][2];
#pragma unroll
            for (int g = 0; g < 2; g++) {
                const int nr = warp_n + g * 16 + (lane & 7) + ((lane >> 4) << 3);
                uint32_t t[4];
                ldsm4(t, st + G1_ARR_B + nr * 80 + (((lane >> 3) & 1) * 16) + kb);
                bh[g * 2][0] = t[0]; bh[g * 2][1] = t[1];
                bh[g * 2 + 1][0] = t[2]; bh[g * 2 + 1][1] = t[3];
            }
#pragma unroll
            for (int mt = 0; mt < 4; mt++)
#pragma unroll
                for (int nt = 0; nt < 4; nt++)
                    mma_f16(acc[mt][nt], ah[mt], bh[nt]);
        }
    }

#pragma unroll
    for (int mt = 0; mt < 4; mt++) {
        const int m = m0 + warp_m + mt * 16 + (lane >> 2);
#pragma unroll
        for (int nt = 0; nt < 4; nt++) {
            const int n = n0 + warp_n + nt * 8 + (lane & 3) * 2;
            const float b0 = bias[n], b1 = bias[n + 1];
            float2 v0 = make_float2(acc[mt][nt][0] + b0, acc[mt][nt][1] + b1);
            float2 v1 = make_float2(acc[mt][nt][2] + b0, acc[mt][nt][3] + b1);
            *(float2*)(C + (size_t)m * NH + n)       = v0;
            *(float2*)(C + (size_t)(m + 8) * NH + n) = v1;
        }
    }
}

// ============================================================================
// t = 0: h0 = tanh(xw[0]); write fp32 out[0] and fp16 state buf 0
// ============================================================================
__global__ __launch_bounds__(256) void tanh0_kernel(float* __restrict__ x)
{
    const size_t i = (size_t)blockIdx.x * blockDim.x + threadIdx.x;  // float4 idx
    float4 v = ((const float4*)x)[i];
    v.x = tanhf(v.x); v.y = tanhf(v.y); v.z = tanhf(v.z); v.w = tanhf(v.w);
    ((float4*)x)[i] = v;
    ((__half2*)g_H16[0])[i * 2 + 0] = __floats2half2_rn(v.x, v.y);
    ((__half2*)g_H16[0])[i * 2 + 1] = __floats2half2_rn(v.z, v.w);
}

// ============================================================================
// Persistent RNN recurrence: t = 1..511.  NO per-chunk pipeline:
// the CTA's whole H slice (32 rows x 1024 fp16 = 64 KB) is loaded per step
// in 2 commit groups; compute K 0..511 overlaps the K 512..1023 stream.
// 128 CTAs = 8 m-groups (32 rows) x 16 n-blocks (64 cols), 256 threads.
// W_hh slice (64 rows x 1024 fp16 = 128 KB) resident, dense swizzled rows.
// Split-K across warps (kh = wid>>2); warp tile 16m x 32n.
// smem: W [0,131072) | H [131072,196608) | rbuf [196608,204800)
// ============================================================================
#define PW_BASE  0
#define PH_BASE  131072
#define PR_BASE  196608
#define PK_SMEM  204800

__global__ __launch_bounds__(256, 1) void rnn_persist_kernel(float* __restrict__ out)
{
    extern __shared__ char smem[];
    const uint32_t sb = smem_u32(smem);
    const int tid  = threadIdx.x;
    const int wid  = tid >> 5;
    const int lane = tid & 31;
    const int mb = blockIdx.x >> 4;    // 0..7  (m-group)
    const int nb = blockIdx.x & 15;    // 0..15
    const int m0 = mb * 32;
    const int n0 = nb * 64;
    const int warp_m = (wid & 1) * 16;        // 0 or 16
    const int warp_n = ((wid >> 1) & 1) * 32; // 0 or 32
    const int kh     = wid >> 2;              // k16 half within each k32 sub

    // ---- Load resident W_hh slice: 64 rows x 128 gsegs, swizzled ----
    for (int idx = tid; idx < 8192; idx += 256) {
        const int r    = idx >> 7;        // 0..63
        const int gseg = idx & 127;       // 0..127
        CP16(sb + PW_BASE + swz(r, gseg),
             g_Whh16 + (size_t)(n0 + r) * NH + gseg * 8);
    }
    CP_COMMIT(); CP_WAIT(0); __syncthreads();

    const int hrow = tid >> 3;   // 0..31
    const int hsb  = tid & 7;    // seg base

    for (int t = 1; t < T_STEPS; t++) {
        const __half* Hh = g_H16[(t - 1) & 1];
        __half* HO = g_H16[t & 1];
        float* X = out + (size_t)t * BATCH * NH;

        // ---- Issue the ENTIRE H slice: 2 commit groups (K halves) ----
        const __half* hsrc = Hh + (size_t)(m0 + hrow) * NH;
        const uint32_t hdst = sb + PH_BASE;
#pragma unroll
        for (int j = 0; j < 8; j++) {
            const int gseg = hsb + j * 8;           // 0..63
            CP16(hdst + swz(hrow, gseg), hsrc + gseg * 8);
        }
        CP_COMMIT();
#pragma unroll
        for (int j = 8; j < 16; j++) {
            const int gseg = hsb + j * 8;           // 64..127
            CP16(hdst + swz(hrow, gseg), hsrc + gseg * 8);
        }
        CP_COMMIT();

        // Prefetch xw tile while H streams (used by kh=0 warps in epilogue)
        float2 xwr[2][4];
        if (kh == 0) {
            const int mrow = m0 + warp_m + (lane >> 2);
#pragma unroll
            for (int half = 0; half < 2; half++)
#pragma unroll
                for (int nt = 0; nt < 4; nt++) {
                    const int m = mrow + half * 8;
                    const int n = n0 + warp_n + nt * 8 + (lane & 3) * 2;
                    xwr[half][nt] = *(const float2*)(X + (size_t)m * NH + n);
                }
        }

        float acc[4][4];
#pragma unroll
        for (int i = 0; i < 4; i++)
#pragma unroll
            for (int j = 0; j < 4; j++) acc[i][j] = 0.f;

        // ---- Compute: subs 0..15 after group A, 16..31 after group B ----
        const int arow = warp_m + (lane & 15);
#pragma unroll
        for (int sub = 0; sub < 32; sub++) {
            if (sub == 0)  { CP_WAIT(1); __syncthreads(); }
            if (sub == 16) { CP_WAIT(0); __syncthreads(); }

            const int gsA = sub * 4 + kh * 2 + (lane >> 4);
            uint32_t ah[4];
            ldsm4(ah, sb + PH_BASE + swz(arow, gsA));

            const int gsB = sub * 4 + kh * 2 + ((lane >> 3) & 1);
            uint32_t bh[4][2];
#pragma unroll
            for (int g = 0; g < 2; g++) {
                const int nr = warp_n + g * 16 + (lane & 7) + ((lane >> 4) << 3);
                uint32_t tmp[4];
                ldsm4(tmp, sb + PW_BASE + swz(nr, gsB));
                bh[g * 2][0] = tmp[0]; bh[g * 2][1] = tmp[1];
                bh[g * 2 + 1][0] = tmp[2]; bh[g * 2 + 1][1] = tmp[3];
            }
#pragma unroll
            for (int nt = 0; nt < 4; nt++) mma_f16(acc[nt], ah, bh[nt]);
        }

        // ---- Cross-warp split-K reduction via smem ----
        __syncthreads();
        float* rbuf = (float*)(smem + PR_BASE);   // 32 x 64 fp32 = 8 KB
        if (kh == 1) {
            const int mrow = warp_m + (lane >> 2);
#pragma unroll
            for (int half = 0; half < 2; half++)
#pragma unroll
                for (int nt = 0; nt < 4; nt++) {
                    const int m = mrow + half * 8;
                    const int n = warp_n + nt * 8 + (lane & 3) * 2;
                    *(float2*)(rbuf + m * 64 + n) = make_float2(
                        acc[nt][half * 2 + 0], acc[nt][half * 2 + 1]);
                }
        }
        __syncthreads();

        // ---- Epilogue (kh=0 warps): h = tanh(xw + self + other) ----
        if (kh == 0) {
            const int mrow = m0 + warp_m + (lane >> 2);
#pragma unroll
            for (int half = 0; half < 2; half++) {
                const int m = mrow + half * 8;
                const int mloc = warp_m + (lane >> 2) + half * 8;
#pragma unroll
                for (int nt = 0; nt < 4; nt++) {
                    const int nloc = warp_n + nt * 8 + (lane & 3) * 2;
                    const int n = n0 + nloc;
                    const size_t off = (size_t)m * NH + n;
                    const float2 other = *(const float2*)(rbuf + mloc * 64 + nloc);
                    const float s0 = acc[nt][half * 2 + 0] + other.x;
                    const float s1 = acc[nt][half * 2 + 1] + other.y;
                    const float v0 = tanhf(xwr[half][nt].x + s0);
                    const float v1 = tanhf(xwr[half][nt].y + s1);
                    *(float2*)(X + off) = make_float2(v0, v1);
                    *(__half2*)(HO + off) = __floats2half2_rn(v0, v1);
                    if (t == T_STEPS - 1)
                        *(float2*)(out + (size_t)T_STEPS * BATCH * NH + off) =
                            make_float2(v0, v1);
                }
            }
        }

        // ---- Per-m-group barrier between steps (16 CTAs) ----
        __syncthreads();
        if (tid == 0) grid_bar(mb);
        __syncthreads();
    }
}

// ============================================================================
// Launch
// ============================================================================
extern "C" void kernel_launch(void* const* d_in, const int* in_sizes, int n_in,
                              void* d_out, int out_size)
{
    const float* inputs = (const float*)d_in[0];   // [T, B, NIN]
    const float* W_xh   = (const float*)d_in[1];   // [NIN, NH]
    const float* W_hh   = (const float*)d_in[2];   // [NH, NH]
    const float* b_h    = (const float*)d_in[3];   // [NH]
    float* out = (float*)d_out;                    // [T, B, NH] + [B, NH]

    const size_t step_elems = (size_t)BATCH * NH;  // 262144

    static bool attr_set = false;
    if (!attr_set) {
        cudaFuncSetAttribute(gemm1_kernel,
                             cudaFuncAttributeMaxDynamicSharedMemorySize, G1_SMEM);
        cudaFuncSetAttribute(rnn_persist_kernel,
                             cudaFuncAttributeMaxDynamicSharedMemorySize, PK_SMEM);
        attr_set = true;
    }

    // Prep: transpose weights to fp16 [N][K]; convert inputs to fp16
    {
        dim3 grid(NH / 32, NIN / 32);
        conv_w16_kernel<<<grid, 256>>>(W_xh, 0);
        conv_w16_kernel<<<grid, 256>>>(W_hh, 1);
        conv_a_kernel<<<8192, 256>>>(inputs);
    }

    // Phase 1: xw = inputs @ W_xh + b_h  -> out[0..T)
    {
        dim3 grid(NH / 128, M_TOTAL / 128);   // (8, 1024)
        gemm1_kernel<<<grid, 256, G1_SMEM>>>(b_h, out);
    }

    // t = 0
    tanh0_kernel<<<(int)(step_elems / 4 / 256), 256>>>(out);

    // t = 1..T-1 in ONE persistent kernel (also writes final_state tail)
    rnn_persist_kernel<<<PK_CTAS, 256, PK_SMEM>>>(out);
}

// round 14
// speedup vs baseline: 3.6411x; 1.0353x over previous
#include <cuda_runtime.h>
#include <cuda_fp16.h>
#include <math.h>
#include <stdint.h>

// Problem shapes (fixed by reference)
#define T_STEPS 512
#define BATCH   256
#define NIN     1024
#define NH      1024
#define M_TOTAL (T_STEPS * BATCH)   // 131072

// ============================================================================
// Device scratch (static — no allocation allowed)
// ============================================================================
__device__ __half g_A16[(size_t)M_TOTAL * NIN];          // inputs fp16, [M][K]
__device__ __half g_Wxh16[(size_t)NH * NIN];             // W_xh^T fp16, [N][K]
__device__ __half g_Whh16[(size_t)NH * NH];              // W_hh^T fp16, [N][K]
__device__ __half g_H16[2][(size_t)BATCH * NH];          // state fp16, double buffered

// Per-m-group barrier state (8 groups of 16 CTAs); zero-init, phase monotonic
__device__ unsigned g_bar_count[8];
__device__ unsigned g_bar_phase[8];

// ============================================================================
// PTX helpers (all sm_80-era: compile for plain compute_103)
// ============================================================================
__device__ __forceinline__ uint32_t smem_u32(const void* p) {
    uint32_t a;
    asm("{ .reg .u64 t; cvta.to.shared.u64 t, %1; cvt.u32.u64 %0, t; }"
        : "=r"(a) : "l"(p));
    return a;
}

#define CP16(dst, src) \
    asm volatile("cp.async.cg.shared.global [%0], [%1], 16;" :: "r"(dst), "l"(src))
#define CP_COMMIT() asm volatile("cp.async.commit_group;" ::: "memory")
#define CP_WAIT(n)  asm volatile("cp.async.wait_group %0;" :: "n"(n) : "memory")

__device__ __forceinline__ void ldsm4(uint32_t r[4], uint32_t addr) {
    asm volatile("ldmatrix.sync.aligned.m8n8.x4.shared.b16 {%0,%1,%2,%3}, [%4];"
                 : "=r"(r[0]), "=r"(r[1]), "=r"(r[2]), "=r"(r[3]) : "r"(addr));
}

__device__ __forceinline__ void mma_f16(float c[4], const uint32_t a[4],
                                        const uint32_t b[2]) {
    asm volatile(
        "mma.sync.aligned.m16n8k16.row.col.f32.f16.f16.f32 "
        "{%0,%1,%2,%3}, {%4,%5,%6,%7}, {%8,%9}, {%0,%1,%2,%3};"
        : "+f"(c[0]), "+f"(c[1]), "+f"(c[2]), "+f"(c[3])
        : "r"(a[0]), "r"(a[1]), "r"(a[2]), "r"(a[3]), "r"(b[0]), "r"(b[1]));
}

__device__ __forceinline__ unsigned ld_acq(const unsigned* p) {
    unsigned v;
    asm volatile("ld.acquire.gpu.global.u32 %0, [%1];" : "=r"(v) : "l"(p) : "memory");
    return v;
}
__device__ __forceinline__ void st_rel(unsigned* p, unsigned v) {
    asm volatile("st.release.gpu.global.u32 [%0], %1;" :: "l"(p), "r"(v) : "memory");
}

#define PK_CTAS  128
#define PK_GROUP 16   // CTAs per m-group barrier

__device__ __forceinline__ void grid_bar(int g) {
    unsigned ph = ld_acq(&g_bar_phase[g]);
    __threadfence();
    unsigned old = atomicAdd(&g_bar_count[g], 1);
    if (old == PK_GROUP - 1) {
        g_bar_count[g] = 0;
        st_rel(&g_bar_phase[g], ph + 1);
    } else {
        while (ld_acq(&g_bar_phase[g]) == ph) { }
    }
}

// Dense 2048B-row layout with XOR swizzle (persist kernel W/H slices).
__device__ __forceinline__ uint32_t swz(int row, int gseg) {
    return (uint32_t)(row * 2048 + (gseg >> 3) * 128 + (((gseg ^ row) & 7) * 16));
}
// Dense 128B-row layout with XOR swizzle (gemm1 K64 chunks). seg 0..7.
__device__ __forceinline__ uint32_t sw128(int row, int seg) {
    return (uint32_t)(row * 128 + (((seg ^ row) & 7) * 16));
}

// ============================================================================
// Prep: transpose a weight [K][N] fp32 -> [N][K] fp16
// ============================================================================
__global__ __launch_bounds__(256) void conv_w16_kernel(const float* __restrict__ W,
                                                       int which)
{
    __shared__ float tile[32][33];
    __half* out16 = which ? g_Whh16 : g_Wxh16;
    const int bx = blockIdx.x * 32;   // n block
    const int by = blockIdx.y * 32;   // k block
    const int tx = threadIdx.x & 31;
    const int ty = threadIdx.x >> 5;
    for (int i = ty; i < 32; i += 8)
        tile[i][tx] = W[(size_t)(by + i) * NH + bx + tx];
    __syncthreads();
    for (int i = ty; i < 32; i += 8) {
        float x = tile[tx][i];                 // W[by+tx][bx+i]
        out16[(size_t)(bx + i) * NIN + by + tx] = __float2half(x);
    }
}

// ============================================================================
// Prep: inputs fp32 [M][K] -> g_A16 fp16 (same layout)
// ============================================================================
__global__ __launch_bounds__(256) void conv_a_kernel(const float* __restrict__ A)
{
    const size_t n4 = (size_t)M_TOTAL * NIN / 4;
    size_t i = (size_t)blockIdx.x * blockDim.x + threadIdx.x;
    const size_t stride = (size_t)gridDim.x * blockDim.x;
    for (; i < n4; i += stride) {
        float4 v = ((const float4*)A)[i];
        ((__half2*)g_A16)[i * 2 + 0] = __floats2half2_rn(v.x, v.y);
        ((__half2*)g_A16)[i * 2 + 1] = __floats2half2_rn(v.z, v.w);
    }
}

// ============================================================================
// Phase 1 GEMM: C[M,N] = A16 @ W16^T + bias  (single-term fp16 HMMA)
// CTA 128m x 256n, 512 thr (16 warps 2x8, warp tile 64x32), K-chunk 64,
// 3 stages, dense 128B rows + XOR swizzle. 16 iterations.
// smem stage: A16 [128 rows x 128B] = 16 KB | W16 [256 rows x 128B] = 32 KB
// ============================================================================
#define G1A_B    16384
#define G1_STAGE 49152
#define G1_SMEM  147456

__global__ __launch_bounds__(512, 1) void gemm1_kernel(
    const float* __restrict__ bias, float* __restrict__ C)
{
    extern __shared__ char smem[];
    const uint32_t sb0 = smem_u32(smem);
    const int tid  = threadIdx.x;
    const int wid  = tid >> 5;
    const int lane = tid & 31;
    const int m0 = blockIdx.y * 128;
    const int n0 = blockIdx.x * 256;
    const int warp_m = (wid >> 3) * 64;   // 0 or 64
    const int warp_n = (wid & 7) * 32;    // 0..224

    float acc[4][4][4];
#pragma unroll
    for (int i = 0; i < 4; i++)
#pragma unroll
        for (int j = 0; j < 4; j++)
#pragma unroll
            for (int k = 0; k < 4; k++) acc[i][j][k] = 0.f;

    // Per-stage loads: A 1024 segs + W 2048 segs = 3072 CP16 / 512 thr = 6 each
    auto issue = [&](int c, int s) {
        const uint32_t st = sb0 + s * G1_STAGE;
        const int kbase = c * 64;
#pragma unroll
        for (int i = 0; i < 6; i++) {
            const int idx = tid + i * 512;
            if (idx < 1024) {
                const int row = idx >> 3, seg = idx & 7;
                CP16(st + sw128(row, seg),
                     g_A16 + (size_t)(m0 + row) * NIN + kbase + seg * 8);
            } else {
                const int j = idx - 1024;
                const int row = j >> 3, seg = j & 7;
                CP16(st + G1A_B + sw128(row, seg),
                     g_Wxh16 + (size_t)(n0 + row) * NIN + kbase + seg * 8);
            }
        }
    };

    issue(0, 0); CP_COMMIT();
    issue(1, 1); CP_COMMIT();

    for (int it = 0; it < 16; it++) {
        CP_WAIT(1);
        __syncthreads();
        if (it + 2 < 16) issue(it + 2, (it + 2) % 3);
        CP_COMMIT();

        const uint32_t st = sb0 + (it % 3) * G1_STAGE;
#pragma unroll
        for (int ks = 0; ks < 4; ks++) {
            uint32_t ah[4][4];
#pragma unroll
            for (int mt = 0; mt < 4; mt++) {
                const int row = warp_m + mt * 16 + (lane & 15);
                const int seg = ks * 2 + (lane >> 4);
                ldsm4(ah[mt], st + sw128(row, seg));
            }
            uint32_t bh[4][2];
#pragma unroll
            for (int g = 0; g < 2; g++) {
                const int row = warp_n + g * 16 + (lane & 7) + ((lane >> 4) << 3);
                const int seg = ks * 2 + ((lane >> 3) & 1);
                uint32_t t[4];
                ldsm4(t, st + G1A_B + sw128(row, seg));
                bh[g * 2][0] = t[0]; bh[g * 2][1] = t[1];
                bh[g * 2 + 1][0] = t[2]; bh[g * 2 + 1][1] = t[3];
            }
#pragma unroll
            for (int mt = 0; mt < 4; mt++)
#pragma unroll
                for (int nt = 0; nt < 4; nt++)
                    mma_f16(acc[mt][nt], ah[mt], bh[nt]);
        }
    }

#pragma unroll
    for (int mt = 0; mt < 4; mt++) {
        const int m = m0 + warp_m + mt * 16 + (lane >> 2);
#pragma unroll
        for (int nt = 0; nt < 4; nt++) {
            const int n = n0 + warp_n + nt * 8 + (lane & 3) * 2;
            const float b0 = bias[n], b1 = bias[n + 1];
            float2 v0 = make_float2(acc[mt][nt][0] + b0, acc[mt][nt][1] + b1);
            float2 v1 = make_float2(acc[mt][nt][2] + b0, acc[mt][nt][3] + b1);
            *(float2*)(C + (size_t)m * NH + n)       = v0;
            *(float2*)(C + (size_t)(m + 8) * NH + n) = v1;
        }
    }
}

// ============================================================================
// t = 0: h0 = tanh(xw[0]); write fp32 out[0] and fp16 state buf 0
// ============================================================================
__global__ __launch_bounds__(256) void tanh0_kernel(float* __restrict__ x)
{
    const size_t i = (size_t)blockIdx.x * blockDim.x + threadIdx.x;  // float4 idx
    float4 v = ((const float4*)x)[i];
    v.x = tanhf(v.x); v.y = tanhf(v.y); v.z = tanhf(v.z); v.w = tanhf(v.w);
    ((float4*)x)[i] = v;
    ((__half2*)g_H16[0])[i * 2 + 0] = __floats2half2_rn(v.x, v.y);
    ((__half2*)g_H16[0])[i * 2 + 1] = __floats2half2_rn(v.z, v.w);
}

// ============================================================================
// Persistent RNN recurrence: t = 1..511.  (R13 configuration — unchanged.)
// 128 CTAs = 8 m-groups (32 rows) x 16 n-blocks (64 cols), 256 threads.
// W_hh slice (64 rows x 1024 fp16 = 128 KB) resident, dense swizzled rows.
// H slice (32 x 1024 = 64 KB) loaded whole per step in 2 commit groups.
// Split-K across warps (kh = wid>>2); warp tile 16m x 32n.
// smem: W [0,131072) | H [131072,196608) | rbuf [196608,204800)
// ============================================================================
#define PW_BASE  0
#define PH_BASE  131072
#define PR_BASE  196608
#define PK_SMEM  204800

__global__ __launch_bounds__(256, 1) void rnn_persist_kernel(float* __restrict__ out)
{
    extern __shared__ char smem[];
    const uint32_t sb = smem_u32(smem);
    const int tid  = threadIdx.x;
    const int wid  = tid >> 5;
    const int lane = tid & 31;
    const int mb = blockIdx.x >> 4;    // 0..7  (m-group)
    const int nb = blockIdx.x & 15;    // 0..15
    const int m0 = mb * 32;
    const int n0 = nb * 64;
    const int warp_m = (wid & 1) * 16;        // 0 or 16
    const int warp_n = ((wid >> 1) & 1) * 32; // 0 or 32
    const int kh     = wid >> 2;              // k16 half within each k32 sub

    // ---- Load resident W_hh slice: 64 rows x 128 gsegs, swizzled ----
    for (int idx = tid; idx < 8192; idx += 256) {
        const int r    = idx >> 7;        // 0..63
        const int gseg = idx & 127;       // 0..127
        CP16(sb + PW_BASE + swz(r, gseg),
             g_Whh16 + (size_t)(n0 + r) * NH + gseg * 8);
    }
    CP_COMMIT(); CP_WAIT(0); __syncthreads();

    const int hrow = tid >> 3;   // 0..31
    const int hsb  = tid & 7;    // seg base

    for (int t = 1; t < T_STEPS; t++) {
        const __half* Hh = g_H16[(t - 1) & 1];
        __half* HO = g_H16[t & 1];
        float* X = out + (size_t)t * BATCH * NH;

        // ---- Issue the ENTIRE H slice: 2 commit groups (K halves) ----
        const __half* hsrc = Hh + (size_t)(m0 + hrow) * NH;
        const uint32_t hdst = sb + PH_BASE;
#pragma unroll
        for (int j = 0; j < 8; j++) {
            const int gseg = hsb + j * 8;           // 0..63
            CP16(hdst + swz(hrow, gseg), hsrc + gseg * 8);
        }
        CP_COMMIT();
#pragma unroll
        for (int j = 8; j < 16; j++) {
            const int gseg = hsb + j * 8;           // 64..127
            CP16(hdst + swz(hrow, gseg), hsrc + gseg * 8);
        }
        CP_COMMIT();

        // Prefetch xw tile while H streams (used by kh=0 warps in epilogue)
        float2 xwr[2][4];
        if (kh == 0) {
            const int mrow = m0 + warp_m + (lane >> 2);
#pragma unroll
            for (int half = 0; half < 2; half++)
#pragma unroll
                for (int nt = 0; nt < 4; nt++) {
                    const int m = mrow + half * 8;
                    const int n = n0 + warp_n + nt * 8 + (lane & 3) * 2;
                    xwr[half][nt] = *(const float2*)(X + (size_t)m * NH + n);
                }
        }

        float acc[4][4];
#pragma unroll
        for (int i = 0; i < 4; i++)
#pragma unroll
            for (int j = 0; j < 4; j++) acc[i][j] = 0.f;

        // ---- Compute: subs 0..15 after group A, 16..31 after group B ----
        const int arow = warp_m + (lane & 15);
#pragma unroll
        for (int sub = 0; sub < 32; sub++) {
            if (sub == 0)  { CP_WAIT(1); __syncthreads(); }
            if (sub == 16) { CP_WAIT(0); __syncthreads(); }

            const int gsA = sub * 4 + kh * 2 + (lane >> 4);
            uint32_t ah[4];
            ldsm4(ah, sb + PH_BASE + swz(arow, gsA));

            const int gsB = sub * 4 + kh * 2 + ((lane >> 3) & 1);
            uint32_t bh[4][2];
#pragma unroll
            for (int g = 0; g < 2; g++) {
                const int nr = warp_n + g * 16 + (lane & 7) + ((lane >> 4) << 3);
                uint32_t tmp[4];
                ldsm4(tmp, sb + PW_BASE + swz(nr, gsB));
                bh[g * 2][0] = tmp[0]; bh[g * 2][1] = tmp[1];
                bh[g * 2 + 1][0] = tmp[2]; bh[g * 2 + 1][1] = tmp[3];
            }
#pragma unroll
            for (int nt = 0; nt < 4; nt++) mma_f16(acc[nt], ah, bh[nt]);
        }

        // ---- Cross-warp split-K reduction via smem ----
        __syncthreads();
        float* rbuf = (float*)(smem + PR_BASE);   // 32 x 64 fp32 = 8 KB
        if (kh == 1) {
            const int mrow = warp_m + (lane >> 2);
#pragma unroll
            for (int half = 0; half < 2; half++)
#pragma unroll
                for (int nt = 0; nt < 4; nt++) {
                    const int m = mrow + half * 8;
                    const int n = warp_n + nt * 8 + (lane & 3) * 2;
                    *(float2*)(rbuf + m * 64 + n) = make_float2(
                        acc[nt][half * 2 + 0], acc[nt][half * 2 + 1]);
                }
        }
        __syncthreads();

        // ---- Epilogue (kh=0 warps): h = tanh(xw + self + other) ----
        if (kh == 0) {
            const int mrow = m0 + warp_m + (lane >> 2);
#pragma unroll
            for (int half = 0; half < 2; half++) {
                const int m = mrow + half * 8;
                const int mloc = warp_m + (lane >> 2) + half * 8;
#pragma unroll
                for (int nt = 0; nt < 4; nt++) {
                    const int nloc = warp_n + nt * 8 + (lane & 3) * 2;
                    const int n = n0 + nloc;
                    const size_t off = (size_t)m * NH + n;
                    const float2 other = *(const float2*)(rbuf + mloc * 64 + nloc);
                    const float s0 = acc[nt][half * 2 + 0] + other.x;
                    const float s1 = acc[nt][half * 2 + 1] + other.y;
                    const float v0 = tanhf(xwr[half][nt].x + s0);
                    const float v1 = tanhf(xwr[half][nt].y + s1);
                    *(float2*)(X + off) = make_float2(v0, v1);
                    *(__half2*)(HO + off) = __floats2half2_rn(v0, v1);
                    if (t == T_STEPS - 1)
                        *(float2*)(out + (size_t)T_STEPS * BATCH * NH + off) =
                            make_float2(v0, v1);
                }
            }
        }

        // ---- Per-m-group barrier between steps (16 CTAs) ----
        __syncthreads();
        if (tid == 0) grid_bar(mb);
        __syncthreads();
    }
}

// ============================================================================
// Launch
// ============================================================================
extern "C" void kernel_launch(void* const* d_in, const int* in_sizes, int n_in,
                              void* d_out, int out_size)
{
    const float* inputs = (const float*)d_in[0];   // [T, B, NIN]
    const float* W_xh   = (const float*)d_in[1];   // [NIN, NH]
    const float* W_hh   = (const float*)d_in[2];   // [NH, NH]
    const float* b_h    = (const float*)d_in[3];   // [NH]
    float* out = (float*)d_out;                    // [T, B, NH] + [B, NH]

    const size_t step_elems = (size_t)BATCH * NH;  // 262144

    static bool attr_set = false;
    if (!attr_set) {
        cudaFuncSetAttribute(gemm1_kernel,
                             cudaFuncAttributeMaxDynamicSharedMemorySize, G1_SMEM);
        cudaFuncSetAttribute(rnn_persist_kernel,
                             cudaFuncAttributeMaxDynamicSharedMemorySize, PK_SMEM);
        attr_set = true;
    }

    // Prep: transpose weights to fp16 [N][K]; convert inputs to fp16
    {
        dim3 grid(NH / 32, NIN / 32);
        conv_w16_kernel<<<grid, 256>>>(W_xh, 0);
        conv_w16_kernel<<<grid, 256>>>(W_hh, 1);
        conv_a_kernel<<<8192, 256>>>(inputs);
    }

    // Phase 1: xw = inputs @ W_xh + b_h  -> out[0..T)
    {
        dim3 grid(NH / 256, M_TOTAL / 128);   // (4, 1024)
        gemm1_kernel<<<grid, 512, G1_SMEM>>>(b_h, out);
    }

    // t = 0
    tanh0_kernel<<<(int)(step_elems / 4 / 256), 256>>>(out);

    // t = 1..T-1 in ONE persistent kernel (also writes final_state tail)
    rnn_persist_kernel<<<PK_CTAS, 256, PK_SMEM>>>(out);
}